// round 3
// baseline (speedup 1.0000x reference)
#include <cuda_runtime.h>
#include <cuda_bf16.h>
#include <cstdint>

// Problem constants (fixed by the reference setup)
#define Lq      2048
#define DMODEL  1024
#define DIN     2048
#define Nst     16
#define DTRANK  64
#define KCONV   4
#define XDBLW   (DTRANK + 2*Nst)   // 96
#define DNTOT   (DIN * Nst)        // 32768

// ---------------------------------------------------------------------------
// Device scratch (allocation-free rule: static __device__ globals)
// ---------------------------------------------------------------------------
__device__ float g_xr[(size_t)Lq * 2 * DIN];          // 32 MB : x @ W_in  (xi_pre | res)
__device__ float g_xi[(size_t)Lq * DIN];              // 16 MB : conv+swish output (u)
__device__ float g_xdbl[(size_t)Lq * XDBLW];          // 0.75MB: [delta_r | B | C]
__device__ float g_xdbl_part[8 * (size_t)Lq * XDBLW]; // split-K partials
__device__ float g_delta[(size_t)Lq * DIN];           // 16 MB
__device__ float g_S[(size_t)Lq * DNTOT];             // 256 MiB suffix sums
__device__ float g_y[(size_t)Lq * DIN];               // 16 MB gated y

// ---------------------------------------------------------------------------
// Math helpers (match JAX formulas)
// ---------------------------------------------------------------------------
__device__ __forceinline__ float softplusf(float x) {
    // jax.nn.softplus = max(x,0) + log1p(exp(-|x|))
    return fmaxf(x, 0.f) + log1pf(expf(-fabsf(x)));
}
__device__ __forceinline__ float swishf(float x) {
    return x / (1.f + expf(-x));
}

// ---------------------------------------------------------------------------
// Generic tiled SGEMM: C[M,N] = A[M,K] * B[K,N] (+bias, +softplus)
// Requirements: M % 128 == 0, K % 8 == 0, N % 4 == 0 (all hold here).
// blockIdx.z = split-K slice: A col offset z*K, B row offset z*K, C += z*czs.
// MODE: 0 = plain, 1 = +bias, 2 = softplus(v + bias)
// ---------------------------------------------------------------------------
template <int MODE>
__global__ __launch_bounds__(256) void sgemm_kernel(
    const float* __restrict__ A, const float* __restrict__ B,
    const float* __restrict__ bias, float* __restrict__ C,
    int M, int N, int K, int lda, int ldb, int ldc, size_t czs)
{
    __shared__ float As[8][128];
    __shared__ float Bs[8][128];

    const int tid = threadIdx.x;
    const int bx = blockIdx.x, by = blockIdx.y, bz = blockIdx.z;
    const int rowBlock = by * 128, colBlock = bx * 128;

    const float* Ab = A + (size_t)bz * K;           // column offset
    const float* Bb = B + (size_t)bz * K * ldb;     // row offset
    float*       Cb = C + (size_t)bz * czs;

    const int aRow = tid >> 1;          // 0..127
    const int aCol = (tid & 1) * 4;     // 0 or 4
    const int bRow = tid >> 5;          // 0..7
    const int bCol = (tid & 31) * 4;    // 0..124

    const int rowBase = (tid >> 4) * 8;
    const int colBase = (tid & 15) * 8;

    float acc[8][8];
#pragma unroll
    for (int i = 0; i < 8; i++)
#pragma unroll
        for (int j = 0; j < 8; j++) acc[i][j] = 0.f;

    for (int k0 = 0; k0 < K; k0 += 8) {
        float4 av = *(const float4*)&Ab[(size_t)(rowBlock + aRow) * lda + k0 + aCol];
        As[aCol + 0][aRow] = av.x;
        As[aCol + 1][aRow] = av.y;
        As[aCol + 2][aRow] = av.z;
        As[aCol + 3][aRow] = av.w;

        float4 bv = make_float4(0.f, 0.f, 0.f, 0.f);
        const int gc = colBlock + bCol;
        if (gc < N) bv = *(const float4*)&Bb[(size_t)(k0 + bRow) * ldb + gc];
        *(float4*)&Bs[bRow][bCol] = bv;

        __syncthreads();
#pragma unroll
        for (int kk = 0; kk < 8; kk++) {
            float ra[8], rb[8];
            *(float4*)&ra[0] = *(const float4*)&As[kk][rowBase];
            *(float4*)&ra[4] = *(const float4*)&As[kk][rowBase + 4];
            *(float4*)&rb[0] = *(const float4*)&Bs[kk][colBase];
            *(float4*)&rb[4] = *(const float4*)&Bs[kk][colBase + 4];
#pragma unroll
            for (int i = 0; i < 8; i++)
#pragma unroll
                for (int j = 0; j < 8; j++)
                    acc[i][j] = fmaf(ra[i], rb[j], acc[i][j]);
        }
        __syncthreads();
    }

#pragma unroll
    for (int i = 0; i < 8; i++) {
        const int gr = rowBlock + rowBase + i;
#pragma unroll
        for (int j = 0; j < 8; j++) {
            const int gc = colBlock + colBase + j;
            if (gc < N) {
                float v = acc[i][j];
                if (MODE == 1) v += bias[gc];
                if (MODE == 2) v = softplusf(v + bias[gc]);
                Cb[(size_t)gr * ldc + gc] = v;
            }
        }
    }
}

// ---------------------------------------------------------------------------
// Split-K reduce for x_dbl (fixed order -> deterministic)
// ---------------------------------------------------------------------------
__global__ void reduce_xdbl_kernel(const float* __restrict__ part, float* __restrict__ out)
{
    const int i = blockIdx.x * blockDim.x + threadIdx.x;
    if (i >= Lq * XDBLW) return;
    float s = 0.f;
#pragma unroll
    for (int k = 0; k < 8; k++) s += part[(size_t)k * Lq * XDBLW + i];
    out[i] = s;
}

// ---------------------------------------------------------------------------
// Depthwise causal conv1d (K=4) + bias + swish.  xr first half -> xi
// ---------------------------------------------------------------------------
__global__ void conv_swish_kernel(const float* __restrict__ xr,
                                  const float* __restrict__ w,
                                  const float* __restrict__ b,
                                  float* __restrict__ xi)
{
    const int idx = blockIdx.x * blockDim.x + threadIdx.x;
    if (idx >= Lq * DIN) return;
    const int d = idx & (DIN - 1);
    const int l = idx >> 11;
    float acc = b[d];
#pragma unroll
    for (int k = 0; k < KCONV; k++) {
        const int ls = l - (KCONV - 1) + k;
        if (ls >= 0) acc = fmaf(w[d * KCONV + k], xr[(size_t)ls * (2 * DIN) + d], acc);
    }
    xi[idx] = swishf(acc);
}

// ---------------------------------------------------------------------------
// Scan backward: suffix sums S[l] = sum_{j>l} delta[j,d]*A[d,n], stored [l][dn]
// One thread per (d,n) chain.
// ---------------------------------------------------------------------------
__global__ void scan_bwd_kernel(const float* __restrict__ delta,
                                const float* __restrict__ A_log,
                                float* __restrict__ Sbuf)
{
    const int dn = blockIdx.x * blockDim.x + threadIdx.x;
    if (dn >= DNTOT) return;
    const int d = dn >> 4;
    const float a = -expf(A_log[dn]);   // A_log laid out (d, n)
    float S = 0.f;
    for (int l0 = Lq - 8; l0 >= 0; l0 -= 8) {
        float dl[8];
#pragma unroll
        for (int i = 0; i < 8; i++) dl[i] = delta[(size_t)(l0 + i) * DIN + d];
#pragma unroll
        for (int i = 7; i >= 0; i--) {
            Sbuf[(size_t)(l0 + i) * DNTOT + dn] = S;   // S = suffix sum from l+1
            S = fmaf(dl[i], a, S);
        }
    }
}

// ---------------------------------------------------------------------------
// Scan forward: replicate reference exactly:
//   E = exp(S);  num = cumsum(delta*u*B*E);  xs = num/(E+1e-12);  y = xs.C + u*D
// Underflow emulation: S < -40 => contribution negligible (reference itself is
// exactly 0 there because exp underflows before eps matters). Then gate by
// swish(res). 16 lanes (n) reduce via shfl; lane n==0 writes y[l,d].
// ---------------------------------------------------------------------------
__global__ void scan_fwd_kernel(const float* __restrict__ delta,
                                const float* __restrict__ xi,
                                const float* __restrict__ xdbl,
                                const float* __restrict__ Dp,
                                const float* __restrict__ xr,
                                const float* __restrict__ Sbuf,
                                float* __restrict__ y)
{
    const int dn = blockIdx.x * blockDim.x + threadIdx.x;
    if (dn >= DNTOT) return;
    const int d = dn >> 4;
    const int n = dn & 15;
    const bool w0 = (n == 0);
    const float Dd = Dp[d];
    float num = 0.f;

    for (int l0 = 0; l0 < Lq; l0 += 8) {
        float Sv[8], uv[8], dv[8], Bv[8], Cv[8], rv[8];
#pragma unroll
        for (int i = 0; i < 8; i++) {
            const size_t l = l0 + i;
            Sv[i] = Sbuf[l * DNTOT + dn];
            uv[i] = xi[l * DIN + d];
            dv[i] = delta[l * DIN + d];
            Bv[i] = xdbl[l * XDBLW + DTRANK + n];
            Cv[i] = xdbl[l * XDBLW + DTRANK + Nst + n];
        }
        if (w0) {
#pragma unroll
            for (int i = 0; i < 8; i++)
                rv[i] = xr[(size_t)(l0 + i) * (2 * DIN) + DIN + d];
        }
#pragma unroll
        for (int i = 0; i < 8; i++) {
            float part = 0.f;
            if (Sv[i] > -40.f) {
                const float E = expf(Sv[i]);
                num = fmaf(dv[i] * uv[i] * Bv[i], E, num);
                part = (num / (E + 1e-12f)) * Cv[i];
            }
            part += __shfl_xor_sync(0xffffffffu, part, 8);
            part += __shfl_xor_sync(0xffffffffu, part, 4);
            part += __shfl_xor_sync(0xffffffffu, part, 2);
            part += __shfl_xor_sync(0xffffffffu, part, 1);
            if (w0) {
                float yy = fmaf(uv[i], Dd, part);
                yy *= swishf(rv[i]);
                y[(size_t)(l0 + i) * DIN + d] = yy;
            }
        }
    }
}

// ---------------------------------------------------------------------------
// Launch
// ---------------------------------------------------------------------------
extern "C" void kernel_launch(void* const* d_in, const int* in_sizes, int n_in,
                              void* d_out, int out_size)
{
    const float* x      = (const float*)d_in[0];   // (L, 1024)
    const float* W_in   = (const float*)d_in[1];   // (1024, 4096)
    const float* conv_w = (const float*)d_in[2];   // (2048, 1, 4)
    const float* conv_b = (const float*)d_in[3];   // (2048)
    const float* W_x    = (const float*)d_in[4];   // (2048, 96)
    const float* W_dt   = (const float*)d_in[5];   // (64, 2048)
    const float* b_dt   = (const float*)d_in[6];   // (2048)
    const float* A_log  = (const float*)d_in[7];   // (2048, 16)
    const float* Dp     = (const float*)d_in[8];   // (2048)
    const float* W_out  = (const float*)d_in[9];   // (2048, 1024)
    const float* b_out  = (const float*)d_in[10];  // (1024)
    float* out = (float*)d_out;

    float *xr, *xi, *xdbl, *xdbl_part, *delta, *Sbuf, *y;
    cudaGetSymbolAddress((void**)&xr, g_xr);
    cudaGetSymbolAddress((void**)&xi, g_xi);
    cudaGetSymbolAddress((void**)&xdbl, g_xdbl);
    cudaGetSymbolAddress((void**)&xdbl_part, g_xdbl_part);
    cudaGetSymbolAddress((void**)&delta, g_delta);
    cudaGetSymbolAddress((void**)&Sbuf, g_S);
    cudaGetSymbolAddress((void**)&y, g_y);

    // 1) x_and_res = x @ W_in      (2048x4096, K=1024)
    {
        dim3 grid((2 * DIN) / 128, Lq / 128, 1);
        sgemm_kernel<0><<<grid, 256>>>(x, W_in, nullptr, xr,
                                       Lq, 2 * DIN, DMODEL, DMODEL, 2 * DIN, 2 * DIN, 0);
    }
    // 2) depthwise causal conv + swish -> xi (u)
    conv_swish_kernel<<<(Lq * DIN) / 256, 256>>>(xr, conv_w, conv_b, xi);

    // 3) x_dbl = xi @ W_x          (2048x96, K=2048) split-K x8, then reduce
    {
        dim3 grid(1, Lq / 128, 8);
        sgemm_kernel<0><<<grid, 256>>>(xi, W_x, nullptr, xdbl_part,
                                       Lq, XDBLW, DIN / 8, DIN, XDBLW, XDBLW,
                                       (size_t)Lq * XDBLW);
        reduce_xdbl_kernel<<<(Lq * XDBLW + 255) / 256, 256>>>(xdbl_part, xdbl);
    }
    // 4) delta = softplus(delta_r @ W_dt + b_dt)   (2048x2048, K=64, lda=96)
    {
        dim3 grid(DIN / 128, Lq / 128, 1);
        sgemm_kernel<2><<<grid, 256>>>(xdbl, W_dt, b_dt, delta,
                                       Lq, DIN, DTRANK, XDBLW, DIN, DIN, 0);
    }
    // 5) selective scan (backward suffix sums, then forward + gate)
    scan_bwd_kernel<<<DNTOT / 256, 256>>>(delta, A_log, Sbuf);
    scan_fwd_kernel<<<DNTOT / 256, 256>>>(delta, xi, xdbl, Dp, xr, Sbuf, y);

    // 6) out = y @ W_out + b_out   (2048x1024, K=2048)
    {
        dim3 grid(DMODEL / 128, Lq / 128, 1);
        sgemm_kernel<1><<<grid, 256>>>(y, W_out, b_out, out,
                                       Lq, DMODEL, DIN, DIN, DMODEL, DMODEL, 0);
    }
    (void)in_sizes; (void)n_in; (void)out_size;
}

// round 6
// speedup vs baseline: 4.7354x; 4.7354x over previous
#include <cuda_runtime.h>
#include <cuda_bf16.h>
#include <cstdint>

#define Lq      2048
#define DMODEL  1024
#define DIN     2048
#define Nst     16
#define DTRANK  64
#define KCONV   4
#define XDBLW   (DTRANK + 2*Nst)   // 96

// ---------------------------------------------------------------------------
// Device scratch (allocation-free rule: __device__ globals)
// ---------------------------------------------------------------------------
__device__ float g_xr[(size_t)Lq * 2 * DIN];          // x @ W_in  (xi_pre | res)
__device__ float g_xi[(size_t)Lq * DIN];              // conv+swish output (u)
__device__ float g_xdbl[(size_t)Lq * XDBLW];          // [delta_r | B | C]
__device__ float g_xdbl_part[8 * (size_t)Lq * XDBLW]; // split-K partials
__device__ float g_delta[(size_t)Lq * DIN];           // softplus output

__device__ __nv_bfloat16 g_xhi[(size_t)Lq * DMODEL],  g_xlo[(size_t)Lq * DMODEL];
__device__ __nv_bfloat16 g_WinT_hi[(size_t)2*DIN * DMODEL], g_WinT_lo[(size_t)2*DIN * DMODEL];
__device__ __nv_bfloat16 g_xihi[(size_t)Lq * DIN], g_xilo[(size_t)Lq * DIN];
__device__ __nv_bfloat16 g_WxT_hi[(size_t)XDBLW * DIN], g_WxT_lo[(size_t)XDBLW * DIN];
__device__ __nv_bfloat16 g_dRhi[(size_t)Lq * DTRANK], g_dRlo[(size_t)Lq * DTRANK];
__device__ __nv_bfloat16 g_WdtT_hi[(size_t)DIN * DTRANK], g_WdtT_lo[(size_t)DIN * DTRANK];
__device__ __nv_bfloat16 g_yhi[(size_t)Lq * DIN], g_ylo[(size_t)Lq * DIN];
__device__ __nv_bfloat16 g_WoutT_hi[(size_t)DMODEL * DIN], g_WoutT_lo[(size_t)DMODEL * DIN];

// ---------------------------------------------------------------------------
// Helpers
// ---------------------------------------------------------------------------
__device__ __forceinline__ float softplusf(float x) {
    return fmaxf(x, 0.f) + log1pf(expf(-fabsf(x)));
}
__device__ __forceinline__ float swishf(float x) { return x / (1.f + expf(-x)); }

__device__ __forceinline__ void split2(float v, __nv_bfloat16& h, __nv_bfloat16& l) {
    h = __float2bfloat16(v);
    l = __float2bfloat16(v - __bfloat162float(h));
}

// m16n8k16 row.col bf16 -> f32 accumulate (sm_80+, compiles for plain sm_103)
__device__ __forceinline__ void mma16816(float acc[4], const uint32_t a[4], const uint32_t b[2]) {
    asm volatile(
        "mma.sync.aligned.m16n8k16.row.col.f32.bf16.bf16.f32 "
        "{%0,%1,%2,%3}, {%4,%5,%6,%7}, {%8,%9}, {%0,%1,%2,%3};"
        : "+f"(acc[0]), "+f"(acc[1]), "+f"(acc[2]), "+f"(acc[3])
        : "r"(a[0]), "r"(a[1]), "r"(a[2]), "r"(a[3]), "r"(b[0]), "r"(b[1]));
}

// ---------------------------------------------------------------------------
// HMMA triple-GEMM (hi/lo split): C[M x N] = A * B^T
//   A: [M, lda] bf16 hi/lo (K-contig), B: [N, ldb] bf16 hi/lo (K-contig)
//   CTA tile 128 x NT (NT = 128 or 96), BK = 32. 256 threads = 8 warps (4m x 2n).
//   blockIdx.z = split-K slice: k offset z*K, C += z*czs.
//   MODE: 0 plain, 1 +bias[col], 2 softplus(v + bias[col])
// ---------------------------------------------------------------------------
#define SKp 40   // padded smem K-stride (bank-conflict-free, rows 16B aligned)

template <int NT, int MODE>
__global__ __launch_bounds__(256) void gemm_mma(
    const __nv_bfloat16* __restrict__ Ahi, const __nv_bfloat16* __restrict__ Alo,
    const __nv_bfloat16* __restrict__ Bhi, const __nv_bfloat16* __restrict__ Blo,
    const float* __restrict__ bias, float* __restrict__ C,
    int K, int lda, int ldb, int ldc, size_t czs)
{
    constexpr int WN = NT / 2;     // warp n-extent (64 or 48)
    constexpr int NF = WN / 8;     // n-frags per warp (8 or 6)

    __shared__ __nv_bfloat16 sAh[128 * SKp], sAl[128 * SKp];
    __shared__ __nv_bfloat16 sBh[128 * SKp], sBl[128 * SKp];

    const int tid = threadIdx.x, lane = tid & 31, wid = tid >> 5;
    const int wm = wid & 3, wn = wid >> 2;
    const int g = lane >> 2, tg = lane & 3;
    const int rowBlock = blockIdx.y * 128;
    const int colBlock = blockIdx.x * NT;
    const int kbase = blockIdx.z * K;
    float* Cb = C + (size_t)blockIdx.z * czs;

    float acc[2][NF][4];
#pragma unroll
    for (int i = 0; i < 2; ++i)
#pragma unroll
        for (int j = 0; j < NF; ++j)
#pragma unroll
            for (int q = 0; q < 4; ++q) acc[i][j][q] = 0.f;

    const int nchunks = K >> 5;
    for (int c = 0; c < nchunks; ++c) {
        const int k0 = kbase + (c << 5);
        // Global -> smem (uint4 = 8 bf16). 512 segments per matrix, 2 per thread.
#pragma unroll
        for (int it = 0; it < 2; ++it) {
            const int i = tid + it * 256;
            const int row = i >> 2, seg = i & 3;
            const size_t ga = (size_t)(rowBlock + row) * lda + k0 + seg * 8;
            *(uint4*)&sAh[row * SKp + seg * 8] = *(const uint4*)(Ahi + ga);
            *(uint4*)&sAl[row * SKp + seg * 8] = *(const uint4*)(Alo + ga);
            if (row < NT) {
                const size_t gb = (size_t)(colBlock + row) * ldb + k0 + seg * 8;
                *(uint4*)&sBh[row * SKp + seg * 8] = *(const uint4*)(Bhi + gb);
                *(uint4*)&sBl[row * SKp + seg * 8] = *(const uint4*)(Blo + gb);
            }
        }
        __syncthreads();

#pragma unroll
        for (int ks = 0; ks < 2; ++ks) {
            const int kk = ks * 16 + 2 * tg;
            uint32_t ah[2][4], al[2][4];
#pragma unroll
            for (int i = 0; i < 2; ++i) {
                const int r0 = wm * 32 + i * 16 + g;
                ah[i][0] = *(const uint32_t*)&sAh[(r0    ) * SKp + kk    ];
                ah[i][1] = *(const uint32_t*)&sAh[(r0 + 8) * SKp + kk    ];
                ah[i][2] = *(const uint32_t*)&sAh[(r0    ) * SKp + kk + 8];
                ah[i][3] = *(const uint32_t*)&sAh[(r0 + 8) * SKp + kk + 8];
                al[i][0] = *(const uint32_t*)&sAl[(r0    ) * SKp + kk    ];
                al[i][1] = *(const uint32_t*)&sAl[(r0 + 8) * SKp + kk    ];
                al[i][2] = *(const uint32_t*)&sAl[(r0    ) * SKp + kk + 8];
                al[i][3] = *(const uint32_t*)&sAl[(r0 + 8) * SKp + kk + 8];
            }
            uint32_t bh[NF][2], bl[NF][2];
#pragma unroll
            for (int j = 0; j < NF; ++j) {
                const int rb = wn * WN + j * 8 + g;
                bh[j][0] = *(const uint32_t*)&sBh[rb * SKp + kk    ];
                bh[j][1] = *(const uint32_t*)&sBh[rb * SKp + kk + 8];
                bl[j][0] = *(const uint32_t*)&sBl[rb * SKp + kk    ];
                bl[j][1] = *(const uint32_t*)&sBl[rb * SKp + kk + 8];
            }
#pragma unroll
            for (int i = 0; i < 2; ++i)
#pragma unroll
                for (int j = 0; j < NF; ++j) {
                    mma16816(acc[i][j], ah[i], bh[j]);
                    mma16816(acc[i][j], ah[i], bl[j]);
                    mma16816(acc[i][j], al[i], bh[j]);
                }
        }
        __syncthreads();
    }

    // Epilogue: fragment layout -> global (float2 per 8-col segment pair)
#pragma unroll
    for (int i = 0; i < 2; ++i) {
#pragma unroll
        for (int j = 0; j < NF; ++j) {
            const int r0 = rowBlock + wm * 32 + i * 16 + g;
            const int c0 = colBlock + wn * WN + j * 8 + 2 * tg;
            float v0 = acc[i][j][0], v1 = acc[i][j][1];
            float v2 = acc[i][j][2], v3 = acc[i][j][3];
            if (MODE == 1) {
                const float b0 = bias[c0], b1 = bias[c0 + 1];
                v0 += b0; v1 += b1; v2 += b0; v3 += b1;
            }
            if (MODE == 2) {
                const float b0 = bias[c0], b1 = bias[c0 + 1];
                v0 = softplusf(v0 + b0); v1 = softplusf(v1 + b1);
                v2 = softplusf(v2 + b0); v3 = softplusf(v3 + b1);
            }
            *(float2*)&Cb[(size_t)(r0    ) * ldc + c0] = make_float2(v0, v1);
            *(float2*)&Cb[(size_t)(r0 + 8) * ldc + c0] = make_float2(v2, v3);
        }
    }
}

// ---------------------------------------------------------------------------
// Split-K reduce for x_dbl (fixed order -> deterministic)
// ---------------------------------------------------------------------------
__global__ void reduce_xdbl_kernel(const float* __restrict__ part, float* __restrict__ out)
{
    const int i = blockIdx.x * blockDim.x + threadIdx.x;
    if (i >= Lq * XDBLW) return;
    float s = 0.f;
#pragma unroll
    for (int k = 0; k < 8; k++) s += part[(size_t)k * Lq * XDBLW + i];
    out[i] = s;
}

// ---------------------------------------------------------------------------
// Transpose + hi/lo split: W [K, N] fp32 -> T [N, K] bf16 hi/lo
// ---------------------------------------------------------------------------
__global__ void transpose_split_kernel(const float* __restrict__ W,
                                       __nv_bfloat16* __restrict__ Th,
                                       __nv_bfloat16* __restrict__ Tl, int K, int N)
{
    __shared__ float t[32][33];
    const int n0 = blockIdx.x * 32, k0 = blockIdx.y * 32;
    const int tx = threadIdx.x, ty = threadIdx.y;
#pragma unroll
    for (int j = 0; j < 32; j += 8)
        t[ty + j][tx] = W[(size_t)(k0 + ty + j) * N + n0 + tx];
    __syncthreads();
#pragma unroll
    for (int j = 0; j < 32; j += 8) {
        const float v = t[tx][ty + j];           // W[k0+tx][n0+ty+j]
        __nv_bfloat16 h, l; split2(v, h, l);
        const size_t o = (size_t)(n0 + ty + j) * K + k0 + tx;
        Th[o] = h; Tl[o] = l;
    }
}

// Elementwise hi/lo split (row-major pass-through)
__global__ void convert_split_kernel(const float* __restrict__ X,
                                     __nv_bfloat16* __restrict__ Xh,
                                     __nv_bfloat16* __restrict__ Xl, int total)
{
    const int i = blockIdx.x * 256 + threadIdx.x;
    if (i >= total) return;
    __nv_bfloat16 h, l; split2(X[i], h, l);
    Xh[i] = h; Xl[i] = l;
}

// xdbl[:, 0:64] -> dR hi/lo [L, 64]
__global__ void convert_dr_kernel(const float* __restrict__ xdbl,
                                  __nv_bfloat16* __restrict__ Rh,
                                  __nv_bfloat16* __restrict__ Rl)
{
    const int i = blockIdx.x * 256 + threadIdx.x;   // i < L*64
    const int l = i >> 6, c = i & 63;
    __nv_bfloat16 h, lo; split2(xdbl[(size_t)l * XDBLW + c], h, lo);
    Rh[i] = h; Rl[i] = lo;
}

// ---------------------------------------------------------------------------
// Depthwise causal conv1d + swish; emits xi fp32 + hi/lo and base y = u*D*swish(res)
// ---------------------------------------------------------------------------
__global__ void conv_kernel(const float* __restrict__ xr, const float* __restrict__ w,
                            const float* __restrict__ cb, const float* __restrict__ Dp,
                            float* __restrict__ xi,
                            __nv_bfloat16* __restrict__ xih, __nv_bfloat16* __restrict__ xil,
                            __nv_bfloat16* __restrict__ yh, __nv_bfloat16* __restrict__ yl)
{
    const int idx = blockIdx.x * 256 + threadIdx.x;
    const int d = idx & (DIN - 1), l = idx >> 11;
    float acc = cb[d];
#pragma unroll
    for (int k = 0; k < KCONV; k++) {
        const int ls = l - (KCONV - 1) + k;
        if (ls >= 0) acc = fmaf(w[d * KCONV + k], xr[(size_t)ls * (2 * DIN) + d], acc);
    }
    const float u = swishf(acc);
    xi[idx] = u;
    { __nv_bfloat16 h, lo; split2(u, h, lo); xih[idx] = h; xil[idx] = lo; }
    const float rv = xr[(size_t)l * (2 * DIN) + DIN + d];
    const float yy = u * Dp[d] * swishf(rv);
    { __nv_bfloat16 h, lo; split2(yy, h, lo); yh[idx] = h; yl[idx] = lo; }
}

// ---------------------------------------------------------------------------
// Selective scan, dead-zone aware (numerically identical to the R3-validated
// -40-cutoff version). One thread per (d,n). Backward pass finds the S = -40
// crossing (reference exp-underflow boundary); forward pass covers only the
// active tail; lane n==0 overwrites the base y written by conv.
// ---------------------------------------------------------------------------
__global__ void scan_kernel(const float* __restrict__ delta, const float* __restrict__ xi,
                            const float* __restrict__ xdbl, const float* __restrict__ Dp,
                            const float* __restrict__ xr, const float* __restrict__ A_log,
                            __nv_bfloat16* __restrict__ yh, __nv_bfloat16* __restrict__ yl)
{
    const int dn = blockIdx.x * 256 + threadIdx.x;
    const int d = dn >> 4, n = dn & 15;
    const float a = -expf(A_log[dn]);

    // Backward: S[l] = suffix sum of dA from l+1 (S[L-1] = 0). Find the first
    // (largest-l) point where S <= -40; S0 = S[l0] of the active start.
    int l0 = 0;
    float S0 = 0.f;
    {
        float S = 0.f;        // S[L-1]
        int l = Lq - 1;
        while (true) {
            if (S <= -40.f) { l0 = l + 1; break; }     // S0 already holds S[l+1]
            if (l == 0)      { l0 = 0; S0 = S; break; }
            S0 = S;
            S += delta[(size_t)l * DIN + d] * a;       // -> S[l-1]
            --l;
        }
    }
    const int wl0 = __reduce_min_sync(0xffffffffu, l0);
    const float Dd = Dp[d];
    const bool w0 = (n == 0);

    float Scur = S0, num = 0.f;
    for (int l = wl0; l < Lq; ++l) {
        const float dv = delta[(size_t)l * DIN + d];
        const float uv = xi[(size_t)l * DIN + d];
        float part = 0.f;
        if (l >= l0) {
            if (l > l0) Scur -= dv * a;                // S[l] = S[l-1] - dA[l]
            if (Scur > -40.f) {
                const float E = expf(Scur);
                num = fmaf(dv * uv * xdbl[(size_t)l * XDBLW + DTRANK + n], E, num);
                part = (num / (E + 1e-12f)) * xdbl[(size_t)l * XDBLW + DTRANK + Nst + n];
            }
        }
        part += __shfl_xor_sync(0xffffffffu, part, 8);
        part += __shfl_xor_sync(0xffffffffu, part, 4);
        part += __shfl_xor_sync(0xffffffffu, part, 2);
        part += __shfl_xor_sync(0xffffffffu, part, 1);
        if (w0) {
            const float rv = xr[(size_t)l * (2 * DIN) + DIN + d];
            const float yy = fmaf(uv, Dd, part) * swishf(rv);
            __nv_bfloat16 h, lo; split2(yy, h, lo);
            yh[(size_t)l * DIN + d] = h;
            yl[(size_t)l * DIN + d] = lo;
        }
    }
}

// ---------------------------------------------------------------------------
// Launch
// ---------------------------------------------------------------------------
extern "C" void kernel_launch(void* const* d_in, const int* in_sizes, int n_in,
                              void* d_out, int out_size)
{
    const float* x      = (const float*)d_in[0];
    const float* W_in   = (const float*)d_in[1];
    const float* conv_w = (const float*)d_in[2];
    const float* conv_b = (const float*)d_in[3];
    const float* W_x    = (const float*)d_in[4];
    const float* W_dt   = (const float*)d_in[5];
    const float* b_dt   = (const float*)d_in[6];
    const float* A_log  = (const float*)d_in[7];
    const float* Dp     = (const float*)d_in[8];
    const float* W_out  = (const float*)d_in[9];
    const float* b_out  = (const float*)d_in[10];
    float* out = (float*)d_out;

    float *xr, *xi, *xdbl, *xdbl_part, *delta;
    cudaGetSymbolAddress((void**)&xr, g_xr);
    cudaGetSymbolAddress((void**)&xi, g_xi);
    cudaGetSymbolAddress((void**)&xdbl, g_xdbl);
    cudaGetSymbolAddress((void**)&xdbl_part, g_xdbl_part);
    cudaGetSymbolAddress((void**)&delta, g_delta);

    __nv_bfloat16 *xhi, *xlo, *WinTh, *WinTl, *xih, *xil, *WxTh, *WxTl;
    __nv_bfloat16 *dRh, *dRl, *WdtTh, *WdtTl, *yh, *yl, *WoutTh, *WoutTl;
    cudaGetSymbolAddress((void**)&xhi, g_xhi);     cudaGetSymbolAddress((void**)&xlo, g_xlo);
    cudaGetSymbolAddress((void**)&WinTh, g_WinT_hi); cudaGetSymbolAddress((void**)&WinTl, g_WinT_lo);
    cudaGetSymbolAddress((void**)&xih, g_xihi);    cudaGetSymbolAddress((void**)&xil, g_xilo);
    cudaGetSymbolAddress((void**)&WxTh, g_WxT_hi); cudaGetSymbolAddress((void**)&WxTl, g_WxT_lo);
    cudaGetSymbolAddress((void**)&dRh, g_dRhi);    cudaGetSymbolAddress((void**)&dRl, g_dRlo);
    cudaGetSymbolAddress((void**)&WdtTh, g_WdtT_hi); cudaGetSymbolAddress((void**)&WdtTl, g_WdtT_lo);
    cudaGetSymbolAddress((void**)&yh, g_yhi);      cudaGetSymbolAddress((void**)&yl, g_ylo);
    cudaGetSymbolAddress((void**)&WoutTh, g_WoutT_hi); cudaGetSymbolAddress((void**)&WoutTl, g_WoutT_lo);

    // Weight transposes + splits (B operands, [N, K] K-contig)
    transpose_split_kernel<<<dim3((2 * DIN) / 32, DMODEL / 32), dim3(32, 8)>>>(W_in, WinTh, WinTl, DMODEL, 2 * DIN);
    transpose_split_kernel<<<dim3(XDBLW / 32, DIN / 32), dim3(32, 8)>>>(W_x, WxTh, WxTl, DIN, XDBLW);
    transpose_split_kernel<<<dim3(DIN / 32, DTRANK / 32), dim3(32, 8)>>>(W_dt, WdtTh, WdtTl, DTRANK, DIN);
    transpose_split_kernel<<<dim3(DMODEL / 32, DIN / 32), dim3(32, 8)>>>(W_out, WoutTh, WoutTl, DIN, DMODEL);
    // A operand split for GEMM1
    convert_split_kernel<<<(Lq * DMODEL) / 256, 256>>>(x, xhi, xlo, Lq * DMODEL);

    // 1) x_and_res = x @ W_in      (2048 x 4096, K=1024)
    gemm_mma<128, 0><<<dim3((2 * DIN) / 128, Lq / 128, 1), 256>>>(
        xhi, xlo, WinTh, WinTl, nullptr, xr, DMODEL, DMODEL, DMODEL, 2 * DIN, 0);

    // 2) conv + swish -> xi (fp32 + hi/lo) and base y = u*D*swish(res)
    conv_kernel<<<(Lq * DIN) / 256, 256>>>(xr, conv_w, conv_b, Dp, xi, xih, xil, yh, yl);

    // 3) x_dbl = xi @ W_x          (2048 x 96, K=2048) split-K x8 + reduce
    gemm_mma<96, 0><<<dim3(1, Lq / 128, 8), 256>>>(
        xih, xil, WxTh, WxTl, nullptr, xdbl_part, DIN / 8, DIN, DIN, XDBLW,
        (size_t)Lq * XDBLW);
    reduce_xdbl_kernel<<<(Lq * XDBLW + 255) / 256, 256>>>(xdbl_part, xdbl);
    convert_dr_kernel<<<(Lq * DTRANK) / 256, 256>>>(xdbl, dRh, dRl);

    // 4) delta = softplus(delta_r @ W_dt + b_dt)   (2048 x 2048, K=64)
    gemm_mma<128, 2><<<dim3(DIN / 128, Lq / 128, 1), 256>>>(
        dRh, dRl, WdtTh, WdtTl, b_dt, delta, DTRANK, DTRANK, DTRANK, DIN, 0);

    // 5) selective scan (active-tail only), overwrites y hi/lo in the tail
    scan_kernel<<<(DIN * Nst) / 256, 256>>>(delta, xi, xdbl, Dp, xr, A_log, yh, yl);

    // 6) out = y @ W_out + b_out   (2048 x 1024, K=2048)
    gemm_mma<128, 1><<<dim3(DMODEL / 128, Lq / 128, 1), 256>>>(
        yh, yl, WoutTh, WoutTl, b_out, out, DIN, DIN, DIN, DMODEL, 0);

    (void)in_sizes; (void)n_in; (void)out_size;
}

// round 8
// speedup vs baseline: 5.5201x; 1.1657x over previous
#include <cuda_runtime.h>
#include <cuda_bf16.h>
#include <cstdint>

#define Lq      2048
#define DMODEL  1024
#define DIN     2048
#define Nst     16
#define DTRANK  64
#define KCONV   4
#define XDBLW   (DTRANK + 2*Nst)   // 96

// ---------------------------------------------------------------------------
// Device scratch (allocation-free rule: __device__ globals)
// ---------------------------------------------------------------------------
__device__ float g_xr[(size_t)Lq * 2 * DIN];          // x @ W_in  (xi_pre | res)
__device__ float g_xi[(size_t)Lq * DIN];              // conv+swish output (u)
__device__ float g_xdbl[(size_t)Lq * XDBLW];          // [delta_r | B | C]
__device__ float g_xdbl_part[8 * (size_t)Lq * XDBLW]; // split-K partials
__device__ float g_delta[(size_t)Lq * DIN];           // softplus output

__device__ __nv_bfloat16 g_xhi[(size_t)Lq * DMODEL],  g_xlo[(size_t)Lq * DMODEL];
__device__ __nv_bfloat16 g_WinT_hi[(size_t)2*DIN * DMODEL], g_WinT_lo[(size_t)2*DIN * DMODEL];
__device__ __nv_bfloat16 g_xihi[(size_t)Lq * DIN], g_xilo[(size_t)Lq * DIN];
__device__ __nv_bfloat16 g_WxT_hi[(size_t)XDBLW * DIN], g_WxT_lo[(size_t)XDBLW * DIN];
__device__ __nv_bfloat16 g_dRhi[(size_t)Lq * DTRANK], g_dRlo[(size_t)Lq * DTRANK];
__device__ __nv_bfloat16 g_WdtT_hi[(size_t)DIN * DTRANK], g_WdtT_lo[(size_t)DIN * DTRANK];
__device__ __nv_bfloat16 g_yhi[(size_t)Lq * DIN], g_ylo[(size_t)Lq * DIN];
__device__ __nv_bfloat16 g_WoutT_hi[(size_t)DMODEL * DIN], g_WoutT_lo[(size_t)DMODEL * DIN];

// ---------------------------------------------------------------------------
// Helpers
// ---------------------------------------------------------------------------
__device__ __forceinline__ float softplusf(float x) {
    return fmaxf(x, 0.f) + log1pf(expf(-fabsf(x)));
}
__device__ __forceinline__ float swishf(float x) { return x / (1.f + expf(-x)); }

__device__ __forceinline__ void split2(float v, __nv_bfloat16& h, __nv_bfloat16& l) {
    h = __float2bfloat16(v);
    l = __float2bfloat16(v - __bfloat162float(h));
}

__device__ __forceinline__ uint32_t smem_u32(const void* p) {
    uint32_t a;
    asm("{ .reg .u64 t; cvta.to.shared.u64 t, %1; cvt.u32.u64 %0, t; }" : "=r"(a) : "l"(p));
    return a;
}

// m16n8k16 row.col bf16 -> f32 accumulate (sm_80+, plain sm_103 OK)
__device__ __forceinline__ void mma16816(float acc[4], const uint32_t a[4], const uint32_t b[2]) {
    asm volatile(
        "mma.sync.aligned.m16n8k16.row.col.f32.bf16.bf16.f32 "
        "{%0,%1,%2,%3}, {%4,%5,%6,%7}, {%8,%9}, {%0,%1,%2,%3};"
        : "+f"(acc[0]), "+f"(acc[1]), "+f"(acc[2]), "+f"(acc[3])
        : "r"(a[0]), "r"(a[1]), "r"(a[2]), "r"(a[3]), "r"(b[0]), "r"(b[1]));
}

__device__ __forceinline__ void ldsm_x4(uint32_t r[4], uint32_t addr) {
    asm volatile("ldmatrix.sync.aligned.m8n8.x4.shared.b16 {%0,%1,%2,%3}, [%4];"
                 : "=r"(r[0]), "=r"(r[1]), "=r"(r[2]), "=r"(r[3]) : "r"(addr));
}

#define CP_ASYNC16(dst_u32, src_ptr) \
    asm volatile("cp.async.cg.shared.global [%0], [%1], 16;" :: "r"(dst_u32), "l"(src_ptr))
#define CP_COMMIT() asm volatile("cp.async.commit_group;" ::: "memory")

// ---------------------------------------------------------------------------
// HMMA triple-GEMM (hi/lo split): C[M x N] = A * B^T
//   A: [M, lda] bf16 hi/lo (K-contig), B: [N, ldb] bf16 hi/lo (K-contig)
//   CTA tile 128 x NT (128 or 96), BK = 32, 3-stage cp.async pipeline,
//   ldmatrix fragment loads. 256 threads = 8 warps (4m x 2n).
//   blockIdx.z = split-K slice: k offset z*K, C += z*czs.
//   MODE: 0 plain, 1 +bias[col], 2 softplus(v + bias[col])
// ---------------------------------------------------------------------------
#define SKp 40                          // padded smem K-stride (conflict-free)
#define MAT_BYTES (128 * SKp * 2)       // 10240 per matrix per stage
#define STAGE_BYTES (4 * MAT_BYTES)     // Ah | Al | Bh | Bl
#define GEMM_SMEM (3 * STAGE_BYTES)     // 122880

template <int NT, int MODE>
__global__ __launch_bounds__(256) void gemm_mma(
    const __nv_bfloat16* __restrict__ Ahi, const __nv_bfloat16* __restrict__ Alo,
    const __nv_bfloat16* __restrict__ Bhi, const __nv_bfloat16* __restrict__ Blo,
    const float* __restrict__ bias, float* __restrict__ C,
    int K, int lda, int ldb, int ldc, size_t czs)
{
    constexpr int WN = NT / 2;     // warp n-extent (64 or 48)
    constexpr int NF = WN / 8;     // n-frags per warp (8 or 6)

    extern __shared__ char dsm[];
    const uint32_t sbase = smem_u32(dsm);

    const int tid = threadIdx.x, lane = tid & 31, wid = tid >> 5;
    const int wm = wid & 3, wn = wid >> 2;
    const int g = lane >> 2, tg = lane & 3;
    const int rowBlock = blockIdx.y * 128;
    const int colBlock = blockIdx.x * NT;
    const int kbase = blockIdx.z * K;
    float* Cb = C + (size_t)blockIdx.z * czs;

    // cp.async per-thread coords: 2 iters x (row = i>>2, 16B seg = i&3)
    const int ldRow0 = tid >> 2, ldSeg = (tid & 3) * 8;          // seg in elems
    // ldmatrix per-lane tile coords
    const int lt = lane >> 3, lr = lane & 7;

    float acc[2][NF][4];
#pragma unroll
    for (int i = 0; i < 2; ++i)
#pragma unroll
        for (int j = 0; j < NF; ++j)
#pragma unroll
            for (int q = 0; q < 4; ++q) acc[i][j][q] = 0.f;

    const int nchunks = K >> 5;

    // ---- async load of chunk c into stage c%3 ----
    auto load_chunk = [&](int c) {
        const int k0 = kbase + (c << 5);
        const uint32_t st = sbase + (uint32_t)(c % 3) * STAGE_BYTES;
#pragma unroll
        for (int it = 0; it < 2; ++it) {
            const int row = ldRow0 + it * 64;
            const uint32_t so = (uint32_t)(row * SKp + ldSeg) * 2;
            const size_t ga = (size_t)(rowBlock + row) * lda + k0 + ldSeg;
            CP_ASYNC16(st + so,                 Ahi + ga);
            CP_ASYNC16(st + MAT_BYTES + so,     Alo + ga);
            if (row < NT) {
                const size_t gb = (size_t)(colBlock + row) * ldb + k0 + ldSeg;
                CP_ASYNC16(st + 2 * MAT_BYTES + so, Bhi + gb);
                CP_ASYNC16(st + 3 * MAT_BYTES + so, Blo + gb);
            }
        }
        CP_COMMIT();
    };

    load_chunk(0);
    if (nchunks > 1) load_chunk(1);

    for (int c = 0; c < nchunks; ++c) {
        if (c + 2 < nchunks) load_chunk(c + 2);
        const int rem = nchunks - c;
        if (rem > 2)       asm volatile("cp.async.wait_group 2;" ::: "memory");
        else if (rem == 2) asm volatile("cp.async.wait_group 1;" ::: "memory");
        else               asm volatile("cp.async.wait_group 0;" ::: "memory");
        __syncthreads();

        const uint32_t st = sbase + (uint32_t)(c % 3) * STAGE_BYTES;
        const uint32_t sAh = st, sAl = st + MAT_BYTES;
        const uint32_t sBh = st + 2 * MAT_BYTES, sBl = st + 3 * MAT_BYTES;

#pragma unroll
        for (int ks = 0; ks < 2; ++ks) {
            const int kk0 = ks * 16;
            // A fragments: 4 tiles per x4 (rows +0/+8, cols +0/+8)
            uint32_t ah[2][4], al[2][4];
#pragma unroll
            for (int i = 0; i < 2; ++i) {
                const int ar = wm * 32 + i * 16 + (lt & 1) * 8 + lr;
                const int ac = kk0 + (lt >> 1) * 8;
                const uint32_t off = (uint32_t)(ar * SKp + ac) * 2;
                ldsm_x4(ah[i], sAh + off);
                ldsm_x4(al[i], sAl + off);
            }
            // B fragments: pairs (j, j+1) per x4
            uint32_t bh[NF][2], bl[NF][2];
#pragma unroll
            for (int j = 0; j < NF; j += 2) {
                const int br = wn * WN + (j + (lt >> 1)) * 8 + lr;
                const int bc = kk0 + (lt & 1) * 8;
                const uint32_t off = (uint32_t)(br * SKp + bc) * 2;
                uint32_t t0[4], t1[4];
                ldsm_x4(t0, sBh + off);
                ldsm_x4(t1, sBl + off);
                bh[j][0] = t0[0]; bh[j][1] = t0[1];
                bh[j + 1][0] = t0[2]; bh[j + 1][1] = t0[3];
                bl[j][0] = t1[0]; bl[j][1] = t1[1];
                bl[j + 1][0] = t1[2]; bl[j + 1][1] = t1[3];
            }
#pragma unroll
            for (int i = 0; i < 2; ++i)
#pragma unroll
                for (int j = 0; j < NF; ++j) {
                    mma16816(acc[i][j], ah[i], bh[j]);
                    mma16816(acc[i][j], ah[i], bl[j]);
                    mma16816(acc[i][j], al[i], bh[j]);
                }
        }
        __syncthreads();
    }

    // Epilogue: fragment layout -> global (float2 per 8-col segment pair)
#pragma unroll
    for (int i = 0; i < 2; ++i) {
#pragma unroll
        for (int j = 0; j < NF; ++j) {
            const int r0 = rowBlock + wm * 32 + i * 16 + g;
            const int c0 = colBlock + wn * WN + j * 8 + 2 * tg;
            float v0 = acc[i][j][0], v1 = acc[i][j][1];
            float v2 = acc[i][j][2], v3 = acc[i][j][3];
            if (MODE == 1) {
                const float b0 = bias[c0], b1 = bias[c0 + 1];
                v0 += b0; v1 += b1; v2 += b0; v3 += b1;
            }
            if (MODE == 2) {
                const float b0 = bias[c0], b1 = bias[c0 + 1];
                v0 = softplusf(v0 + b0); v1 = softplusf(v1 + b1);
                v2 = softplusf(v2 + b0); v3 = softplusf(v3 + b1);
            }
            *(float2*)&Cb[(size_t)(r0    ) * ldc + c0] = make_float2(v0, v1);
            *(float2*)&Cb[(size_t)(r0 + 8) * ldc + c0] = make_float2(v2, v3);
        }
    }
}

// ---------------------------------------------------------------------------
// Split-K reduce for x_dbl (fixed order -> deterministic)
// ---------------------------------------------------------------------------
__global__ void reduce_xdbl_kernel(const float* __restrict__ part, float* __restrict__ out)
{
    const int i = blockIdx.x * blockDim.x + threadIdx.x;
    if (i >= Lq * XDBLW) return;
    float s = 0.f;
#pragma unroll
    for (int k = 0; k < 8; k++) s += part[(size_t)k * Lq * XDBLW + i];
    out[i] = s;
}

// ---------------------------------------------------------------------------
// Transpose + hi/lo split: W [K, N] fp32 -> T [N, K] bf16 hi/lo
// ---------------------------------------------------------------------------
__global__ void transpose_split_kernel(const float* __restrict__ W,
                                       __nv_bfloat16* __restrict__ Th,
                                       __nv_bfloat16* __restrict__ Tl, int K, int N)
{
    __shared__ float t[32][33];
    const int n0 = blockIdx.x * 32, k0 = blockIdx.y * 32;
    const int tx = threadIdx.x, ty = threadIdx.y;
#pragma unroll
    for (int j = 0; j < 32; j += 8)
        t[ty + j][tx] = W[(size_t)(k0 + ty + j) * N + n0 + tx];
    __syncthreads();
#pragma unroll
    for (int j = 0; j < 32; j += 8) {
        const float v = t[tx][ty + j];           // W[k0+tx][n0+ty+j]
        __nv_bfloat16 h, l; split2(v, h, l);
        const size_t o = (size_t)(n0 + ty + j) * K + k0 + tx;
        Th[o] = h; Tl[o] = l;
    }
}

// Elementwise hi/lo split (row-major pass-through)
__global__ void convert_split_kernel(const float* __restrict__ X,
                                     __nv_bfloat16* __restrict__ Xh,
                                     __nv_bfloat16* __restrict__ Xl, int total)
{
    const int i = blockIdx.x * 256 + threadIdx.x;
    if (i >= total) return;
    __nv_bfloat16 h, l; split2(X[i], h, l);
    Xh[i] = h; Xl[i] = l;
}

// xdbl[:, 0:64] -> dR hi/lo [L, 64]
__global__ void convert_dr_kernel(const float* __restrict__ xdbl,
                                  __nv_bfloat16* __restrict__ Rh,
                                  __nv_bfloat16* __restrict__ Rl)
{
    const int i = blockIdx.x * 256 + threadIdx.x;   // i < L*64
    const int l = i >> 6, c = i & 63;
    __nv_bfloat16 h, lo; split2(xdbl[(size_t)l * XDBLW + c], h, lo);
    Rh[i] = h; Rl[i] = lo;
}

// ---------------------------------------------------------------------------
// Depthwise causal conv1d + swish; emits xi fp32 + hi/lo and base y = u*D*swish(res)
// ---------------------------------------------------------------------------
__global__ void conv_kernel(const float* __restrict__ xr, const float* __restrict__ w,
                            const float* __restrict__ cb, const float* __restrict__ Dp,
                            float* __restrict__ xi,
                            __nv_bfloat16* __restrict__ xih, __nv_bfloat16* __restrict__ xil,
                            __nv_bfloat16* __restrict__ yh, __nv_bfloat16* __restrict__ yl)
{
    const int idx = blockIdx.x * 256 + threadIdx.x;
    const int d = idx & (DIN - 1), l = idx >> 11;
    float acc = cb[d];
#pragma unroll
    for (int k = 0; k < KCONV; k++) {
        const int ls = l - (KCONV - 1) + k;
        if (ls >= 0) acc = fmaf(w[d * KCONV + k], xr[(size_t)ls * (2 * DIN) + d], acc);
    }
    const float u = swishf(acc);
    xi[idx] = u;
    { __nv_bfloat16 h, lo; split2(u, h, lo); xih[idx] = h; xil[idx] = lo; }
    const float rv = xr[(size_t)l * (2 * DIN) + DIN + d];
    const float yy = u * Dp[d] * swishf(rv);
    { __nv_bfloat16 h, lo; split2(yy, h, lo); yh[idx] = h; yl[idx] = lo; }
}

// ---------------------------------------------------------------------------
// Selective scan, dead-zone aware (R3/R6-validated -40 cutoff logic).
// ---------------------------------------------------------------------------
__global__ void scan_kernel(const float* __restrict__ delta, const float* __restrict__ xi,
                            const float* __restrict__ xdbl, const float* __restrict__ Dp,
                            const float* __restrict__ xr, const float* __restrict__ A_log,
                            __nv_bfloat16* __restrict__ yh, __nv_bfloat16* __restrict__ yl)
{
    const int dn = blockIdx.x * 256 + threadIdx.x;
    const int d = dn >> 4, n = dn & 15;
    const float a = -expf(A_log[dn]);

    int l0 = 0;
    float S0 = 0.f;
    {
        float S = 0.f;        // S[L-1]
        int l = Lq - 1;
        while (true) {
            if (S <= -40.f) { l0 = l + 1; break; }
            if (l == 0)      { l0 = 0; S0 = S; break; }
            S0 = S;
            S += delta[(size_t)l * DIN + d] * a;
            --l;
        }
    }
    const int wl0 = __reduce_min_sync(0xffffffffu, l0);
    const float Dd = Dp[d];
    const bool w0 = (n == 0);

    float Scur = S0, num = 0.f;
    for (int l = wl0; l < Lq; ++l) {
        const float dv = delta[(size_t)l * DIN + d];
        const float uv = xi[(size_t)l * DIN + d];
        float part = 0.f;
        if (l >= l0) {
            if (l > l0) Scur -= dv * a;
            if (Scur > -40.f) {
                const float E = expf(Scur);
                num = fmaf(dv * uv * xdbl[(size_t)l * XDBLW + DTRANK + n], E, num);
                part = (num / (E + 1e-12f)) * xdbl[(size_t)l * XDBLW + DTRANK + Nst + n];
            }
        }
        part += __shfl_xor_sync(0xffffffffu, part, 8);
        part += __shfl_xor_sync(0xffffffffu, part, 4);
        part += __shfl_xor_sync(0xffffffffu, part, 2);
        part += __shfl_xor_sync(0xffffffffu, part, 1);
        if (w0) {
            const float rv = xr[(size_t)l * (2 * DIN) + DIN + d];
            const float yy = fmaf(uv, Dd, part) * swishf(rv);
            __nv_bfloat16 h, lo; split2(yy, h, lo);
            yh[(size_t)l * DIN + d] = h;
            yl[(size_t)l * DIN + d] = lo;
        }
    }
}

// ---------------------------------------------------------------------------
// Launch
// ---------------------------------------------------------------------------
extern "C" void kernel_launch(void* const* d_in, const int* in_sizes, int n_in,
                              void* d_out, int out_size)
{
    const float* x      = (const float*)d_in[0];
    const float* W_in   = (const float*)d_in[1];
    const float* conv_w = (const float*)d_in[2];
    const float* conv_b = (const float*)d_in[3];
    const float* W_x    = (const float*)d_in[4];
    const float* W_dt   = (const float*)d_in[5];
    const float* b_dt   = (const float*)d_in[6];
    const float* A_log  = (const float*)d_in[7];
    const float* Dp     = (const float*)d_in[8];
    const float* W_out  = (const float*)d_in[9];
    const float* b_out  = (const float*)d_in[10];
    float* out = (float*)d_out;

    float *xr, *xi, *xdbl, *xdbl_part, *delta;
    cudaGetSymbolAddress((void**)&xr, g_xr);
    cudaGetSymbolAddress((void**)&xi, g_xi);
    cudaGetSymbolAddress((void**)&xdbl, g_xdbl);
    cudaGetSymbolAddress((void**)&xdbl_part, g_xdbl_part);
    cudaGetSymbolAddress((void**)&delta, g_delta);

    __nv_bfloat16 *xhi, *xlo, *WinTh, *WinTl, *xih, *xil, *WxTh, *WxTl;
    __nv_bfloat16 *dRh, *dRl, *WdtTh, *WdtTl, *yh, *yl, *WoutTh, *WoutTl;
    cudaGetSymbolAddress((void**)&xhi, g_xhi);     cudaGetSymbolAddress((void**)&xlo, g_xlo);
    cudaGetSymbolAddress((void**)&WinTh, g_WinT_hi); cudaGetSymbolAddress((void**)&WinTl, g_WinT_lo);
    cudaGetSymbolAddress((void**)&xih, g_xihi);    cudaGetSymbolAddress((void**)&xil, g_xilo);
    cudaGetSymbolAddress((void**)&WxTh, g_WxT_hi); cudaGetSymbolAddress((void**)&WxTl, g_WxT_lo);
    cudaGetSymbolAddress((void**)&dRh, g_dRhi);    cudaGetSymbolAddress((void**)&dRl, g_dRlo);
    cudaGetSymbolAddress((void**)&WdtTh, g_WdtT_hi); cudaGetSymbolAddress((void**)&WdtTl, g_WdtT_lo);
    cudaGetSymbolAddress((void**)&yh, g_yhi);      cudaGetSymbolAddress((void**)&yl, g_ylo);
    cudaGetSymbolAddress((void**)&WoutTh, g_WoutT_hi); cudaGetSymbolAddress((void**)&WoutTl, g_WoutT_lo);

    cudaFuncSetAttribute(gemm_mma<128, 0>, cudaFuncAttributeMaxDynamicSharedMemorySize, GEMM_SMEM);
    cudaFuncSetAttribute(gemm_mma<96, 0>,  cudaFuncAttributeMaxDynamicSharedMemorySize, GEMM_SMEM);
    cudaFuncSetAttribute(gemm_mma<128, 1>, cudaFuncAttributeMaxDynamicSharedMemorySize, GEMM_SMEM);
    cudaFuncSetAttribute(gemm_mma<128, 2>, cudaFuncAttributeMaxDynamicSharedMemorySize, GEMM_SMEM);

    // Weight transposes + splits (B operands, [N, K] K-contig)
    transpose_split_kernel<<<dim3((2 * DIN) / 32, DMODEL / 32), dim3(32, 8)>>>(W_in, WinTh, WinTl, DMODEL, 2 * DIN);
    transpose_split_kernel<<<dim3(XDBLW / 32, DIN / 32), dim3(32, 8)>>>(W_x, WxTh, WxTl, DIN, XDBLW);
    transpose_split_kernel<<<dim3(DIN / 32, DTRANK / 32), dim3(32, 8)>>>(W_dt, WdtTh, WdtTl, DTRANK, DIN);
    transpose_split_kernel<<<dim3(DMODEL / 32, DIN / 32), dim3(32, 8)>>>(W_out, WoutTh, WoutTl, DIN, DMODEL);
    // A operand split for GEMM1
    convert_split_kernel<<<(Lq * DMODEL) / 256, 256>>>(x, xhi, xlo, Lq * DMODEL);

    // 1) x_and_res = x @ W_in      (2048 x 4096, K=1024)
    gemm_mma<128, 0><<<dim3((2 * DIN) / 128, Lq / 128, 1), 256, GEMM_SMEM>>>(
        xhi, xlo, WinTh, WinTl, nullptr, xr, DMODEL, DMODEL, DMODEL, 2 * DIN, 0);

    // 2) conv + swish -> xi (fp32 + hi/lo) and base y = u*D*swish(res)
    conv_kernel<<<(Lq * DIN) / 256, 256>>>(xr, conv_w, conv_b, Dp, xi, xih, xil, yh, yl);

    // 3) x_dbl = xi @ W_x          (2048 x 96, K=2048) split-K x8 + reduce
    gemm_mma<96, 0><<<dim3(1, Lq / 128, 8), 256, GEMM_SMEM>>>(
        xih, xil, WxTh, WxTl, nullptr, xdbl_part, DIN / 8, DIN, DIN, XDBLW,
        (size_t)Lq * XDBLW);
    reduce_xdbl_kernel<<<(Lq * XDBLW + 255) / 256, 256>>>(xdbl_part, xdbl);
    convert_dr_kernel<<<(Lq * DTRANK) / 256, 256>>>(xdbl, dRh, dRl);

    // 4) delta = softplus(delta_r @ W_dt + b_dt)   (2048 x 2048, K=64)
    gemm_mma<128, 2><<<dim3(DIN / 128, Lq / 128, 1), 256, GEMM_SMEM>>>(
        dRh, dRl, WdtTh, WdtTl, b_dt, delta, DTRANK, DTRANK, DTRANK, DIN, 0);

    // 5) selective scan (active-tail only), overwrites y hi/lo in the tail
    scan_kernel<<<(DIN * Nst) / 256, 256>>>(delta, xi, xdbl, Dp, xr, A_log, yh, yl);

    // 6) out = y @ W_out + b_out   (2048 x 1024, K=2048)
    gemm_mma<128, 1><<<dim3(DMODEL / 128, Lq / 128, 1), 256, GEMM_SMEM>>>(
        yh, yl, WoutTh, WoutTl, b_out, out, DIN, DIN, DIN, DMODEL, 0);

    (void)in_sizes; (void)n_in; (void)out_size;
}

// round 9
// speedup vs baseline: 7.2793x; 1.3187x over previous
#include <cuda_runtime.h>
#include <cuda_bf16.h>
#include <cuda_fp16.h>
#include <cstdint>

#define Lq      2048
#define DMODEL  1024
#define DIN     2048
#define Nst     16
#define DTRANK  64
#define KCONV   4
#define XDBLW   (DTRANK + 2*Nst)   // 96

// ---------------------------------------------------------------------------
// Device scratch (allocation-free rule: __device__ globals)
// ---------------------------------------------------------------------------
__device__ float g_xr[(size_t)Lq * 2 * DIN];          // x @ W_in  (xi_pre | res)
__device__ float g_xi[(size_t)Lq * DIN];              // conv+swish output (u)
__device__ float g_xdbl[(size_t)Lq * XDBLW];          // [delta_r | B | C]
__device__ float g_xdbl_part[8 * (size_t)Lq * XDBLW]; // split-K partials
__device__ float g_delta[(size_t)Lq * DIN];           // softplus output

// A operands: exact fp16 hi/lo pairs. B operands (weights): single fp16.
__device__ __half g_xhi[(size_t)Lq * DMODEL],  g_xlo[(size_t)Lq * DMODEL];
__device__ __half g_WinT[(size_t)2*DIN * DMODEL];
__device__ __half g_xihi[(size_t)Lq * DIN], g_xilo[(size_t)Lq * DIN];
__device__ __half g_WxT[(size_t)XDBLW * DIN];
__device__ __half g_dRhi[(size_t)Lq * DTRANK], g_dRlo[(size_t)Lq * DTRANK];
__device__ __half g_WdtT[(size_t)DIN * DTRANK];
__device__ __half g_yhi[(size_t)Lq * DIN], g_ylo[(size_t)Lq * DIN];
__device__ __half g_WoutT[(size_t)DMODEL * DIN];

// ---------------------------------------------------------------------------
// Helpers
// ---------------------------------------------------------------------------
__device__ __forceinline__ float softplusf(float x) {
    return fmaxf(x, 0.f) + log1pf(expf(-fabsf(x)));
}
__device__ __forceinline__ float swishf(float x) { return x / (1.f + expf(-x)); }

__device__ __forceinline__ void split2h(float v, __half& h, __half& l) {
    h = __float2half(v);
    l = __float2half(v - __half2float(h));
}

__device__ __forceinline__ uint32_t smem_u32(const void* p) {
    uint32_t a;
    asm("{ .reg .u64 t; cvta.to.shared.u64 t, %1; cvt.u32.u64 %0, t; }" : "=r"(a) : "l"(p));
    return a;
}

// m16n8k16 row.col fp16 -> f32 accumulate (sm_80+, plain sm_103 OK)
__device__ __forceinline__ void mma16816h(float acc[4], const uint32_t a[4], const uint32_t b[2]) {
    asm volatile(
        "mma.sync.aligned.m16n8k16.row.col.f32.f16.f16.f32 "
        "{%0,%1,%2,%3}, {%4,%5,%6,%7}, {%8,%9}, {%0,%1,%2,%3};"
        : "+f"(acc[0]), "+f"(acc[1]), "+f"(acc[2]), "+f"(acc[3])
        : "r"(a[0]), "r"(a[1]), "r"(a[2]), "r"(a[3]), "r"(b[0]), "r"(b[1]));
}

__device__ __forceinline__ void ldsm_x4(uint32_t r[4], uint32_t addr) {
    asm volatile("ldmatrix.sync.aligned.m8n8.x4.shared.b16 {%0,%1,%2,%3}, [%4];"
                 : "=r"(r[0]), "=r"(r[1]), "=r"(r[2]), "=r"(r[3]) : "r"(addr));
}

#define CP_ASYNC16(dst_u32, src_ptr) \
    asm volatile("cp.async.cg.shared.global [%0], [%1], 16;" :: "r"(dst_u32), "l"(src_ptr))
#define CP_COMMIT() asm volatile("cp.async.commit_group;" ::: "memory")

// ---------------------------------------------------------------------------
// HMMA 2-pass GEMM (A fp16-pair exact, B fp16 single): C[M x N] = A * B^T
//   A: [M, lda] fp16 hi/lo (K-contig), B: [N, ldb] fp16 (K-contig)
//   CTA tile 128 x NT (128 or 96), BK = 32, 3-stage cp.async pipeline,
//   ldmatrix fragment loads. 256 threads = 8 warps (4m x 2n).
//   blockIdx.z = split-K slice: k offset z*K, C += z*czs.
//   MODE: 0 plain, 1 +bias[col], 2 softplus(v + bias[col])
// ---------------------------------------------------------------------------
#define SKp 40                          // padded smem K-stride (conflict-free)
#define MAT_BYTES (128 * SKp * 2)       // 10240 per matrix per stage
#define STAGE_BYTES (3 * MAT_BYTES)     // Ah | Al | Bh
#define GEMM_SMEM (3 * STAGE_BYTES)     // 92160

template <int NT, int MODE>
__global__ __launch_bounds__(256) void gemm_mma(
    const __half* __restrict__ Ahi, const __half* __restrict__ Alo,
    const __half* __restrict__ Bh16,
    const float* __restrict__ bias, float* __restrict__ C,
    int K, int lda, int ldb, int ldc, size_t czs)
{
    constexpr int WN = NT / 2;     // warp n-extent (64 or 48)
    constexpr int NF = WN / 8;     // n-frags per warp (8 or 6)

    extern __shared__ char dsm[];
    const uint32_t sbase = smem_u32(dsm);

    const int tid = threadIdx.x, lane = tid & 31, wid = tid >> 5;
    const int wm = wid & 3, wn = wid >> 2;
    const int g = lane >> 2, tg = lane & 3;
    const int rowBlock = blockIdx.y * 128;
    const int colBlock = blockIdx.x * NT;
    const int kbase = blockIdx.z * K;
    float* Cb = C + (size_t)blockIdx.z * czs;

    const int ldRow0 = tid >> 2, ldSeg = (tid & 3) * 8;   // cp.async coords
    const int lt = lane >> 3, lr = lane & 7;              // ldmatrix coords

    float acc[2][NF][4];
#pragma unroll
    for (int i = 0; i < 2; ++i)
#pragma unroll
        for (int j = 0; j < NF; ++j)
#pragma unroll
            for (int q = 0; q < 4; ++q) acc[i][j][q] = 0.f;

    const int nchunks = K >> 5;

    auto load_chunk = [&](int c) {
        const int k0 = kbase + (c << 5);
        const uint32_t st = sbase + (uint32_t)(c % 3) * STAGE_BYTES;
#pragma unroll
        for (int it = 0; it < 2; ++it) {
            const int row = ldRow0 + it * 64;
            const uint32_t so = (uint32_t)(row * SKp + ldSeg) * 2;
            const size_t ga = (size_t)(rowBlock + row) * lda + k0 + ldSeg;
            CP_ASYNC16(st + so,             Ahi + ga);
            CP_ASYNC16(st + MAT_BYTES + so, Alo + ga);
            if (row < NT) {
                const size_t gb = (size_t)(colBlock + row) * ldb + k0 + ldSeg;
                CP_ASYNC16(st + 2 * MAT_BYTES + so, Bh16 + gb);
            }
        }
        CP_COMMIT();
    };

    load_chunk(0);
    if (nchunks > 1) load_chunk(1);

    for (int c = 0; c < nchunks; ++c) {
        if (c + 2 < nchunks) load_chunk(c + 2);
        const int rem = nchunks - c;
        if (rem > 2)       asm volatile("cp.async.wait_group 2;" ::: "memory");
        else if (rem == 2) asm volatile("cp.async.wait_group 1;" ::: "memory");
        else               asm volatile("cp.async.wait_group 0;" ::: "memory");
        __syncthreads();

        const uint32_t st = sbase + (uint32_t)(c % 3) * STAGE_BYTES;
        const uint32_t sAh = st, sAl = st + MAT_BYTES, sBh = st + 2 * MAT_BYTES;

#pragma unroll
        for (int ks = 0; ks < 2; ++ks) {
            const int kk0 = ks * 16;
            uint32_t ah[2][4], al[2][4];
#pragma unroll
            for (int i = 0; i < 2; ++i) {
                const int ar = wm * 32 + i * 16 + (lt & 1) * 8 + lr;
                const int ac = kk0 + (lt >> 1) * 8;
                const uint32_t off = (uint32_t)(ar * SKp + ac) * 2;
                ldsm_x4(ah[i], sAh + off);
                ldsm_x4(al[i], sAl + off);
            }
            uint32_t bh[NF][2];
#pragma unroll
            for (int j = 0; j < NF; j += 2) {
                const int br = wn * WN + (j + (lt >> 1)) * 8 + lr;
                const int bc = kk0 + (lt & 1) * 8;
                const uint32_t off = (uint32_t)(br * SKp + bc) * 2;
                uint32_t t0[4];
                ldsm_x4(t0, sBh + off);
                bh[j][0] = t0[0]; bh[j][1] = t0[1];
                bh[j + 1][0] = t0[2]; bh[j + 1][1] = t0[3];
            }
#pragma unroll
            for (int i = 0; i < 2; ++i)
#pragma unroll
                for (int j = 0; j < NF; ++j) {
                    mma16816h(acc[i][j], ah[i], bh[j]);
                    mma16816h(acc[i][j], al[i], bh[j]);
                }
        }
        __syncthreads();
    }

    // Epilogue: fragment layout -> global (float2 per 8-col segment pair)
#pragma unroll
    for (int i = 0; i < 2; ++i) {
#pragma unroll
        for (int j = 0; j < NF; ++j) {
            const int r0 = rowBlock + wm * 32 + i * 16 + g;
            const int c0 = colBlock + wn * WN + j * 8 + 2 * tg;
            float v0 = acc[i][j][0], v1 = acc[i][j][1];
            float v2 = acc[i][j][2], v3 = acc[i][j][3];
            if (MODE == 1) {
                const float b0 = bias[c0], b1 = bias[c0 + 1];
                v0 += b0; v1 += b1; v2 += b0; v3 += b1;
            }
            if (MODE == 2) {
                const float b0 = bias[c0], b1 = bias[c0 + 1];
                v0 = softplusf(v0 + b0); v1 = softplusf(v1 + b1);
                v2 = softplusf(v2 + b0); v3 = softplusf(v3 + b1);
            }
            *(float2*)&Cb[(size_t)(r0    ) * ldc + c0] = make_float2(v0, v1);
            *(float2*)&Cb[(size_t)(r0 + 8) * ldc + c0] = make_float2(v2, v3);
        }
    }
}

// ---------------------------------------------------------------------------
// Split-K reduce for x_dbl (fixed order -> deterministic)
// ---------------------------------------------------------------------------
__global__ void reduce_xdbl_kernel(const float* __restrict__ part, float* __restrict__ out)
{
    const int i = blockIdx.x * blockDim.x + threadIdx.x;
    if (i >= Lq * XDBLW) return;
    float s = 0.f;
#pragma unroll
    for (int k = 0; k < 8; k++) s += part[(size_t)k * Lq * XDBLW + i];
    out[i] = s;
}

// ---------------------------------------------------------------------------
// Transpose: W [K, N] fp32 -> T [N, K] fp16 (single, rounded)
// ---------------------------------------------------------------------------
__global__ void transpose_h_kernel(const float* __restrict__ W,
                                   __half* __restrict__ Th, int K, int N)
{
    __shared__ float t[32][33];
    const int n0 = blockIdx.x * 32, k0 = blockIdx.y * 32;
    const int tx = threadIdx.x, ty = threadIdx.y;
#pragma unroll
    for (int j = 0; j < 32; j += 8)
        t[ty + j][tx] = W[(size_t)(k0 + ty + j) * N + n0 + tx];
    __syncthreads();
#pragma unroll
    for (int j = 0; j < 32; j += 8)
        Th[(size_t)(n0 + ty + j) * K + k0 + tx] = __float2half(t[tx][ty + j]);
}

// Elementwise fp16 hi/lo split (row-major pass-through)
__global__ void convert_split_kernel(const float* __restrict__ X,
                                     __half* __restrict__ Xh,
                                     __half* __restrict__ Xl, int total)
{
    const int i = blockIdx.x * 256 + threadIdx.x;
    if (i >= total) return;
    __half h, l; split2h(X[i], h, l);
    Xh[i] = h; Xl[i] = l;
}

// xdbl[:, 0:64] -> dR hi/lo [L, 64]
__global__ void convert_dr_kernel(const float* __restrict__ xdbl,
                                  __half* __restrict__ Rh,
                                  __half* __restrict__ Rl)
{
    const int i = blockIdx.x * 256 + threadIdx.x;   // i < L*64
    const int l = i >> 6, c = i & 63;
    __half h, lo; split2h(xdbl[(size_t)l * XDBLW + c], h, lo);
    Rh[i] = h; Rl[i] = lo;
}

// ---------------------------------------------------------------------------
// Depthwise causal conv1d + swish; emits xi fp32 + fp16 pair and base
// y = u*D*swish(res) as fp16 pair
// ---------------------------------------------------------------------------
__global__ void conv_kernel(const float* __restrict__ xr, const float* __restrict__ w,
                            const float* __restrict__ cb, const float* __restrict__ Dp,
                            float* __restrict__ xi,
                            __half* __restrict__ xih, __half* __restrict__ xil,
                            __half* __restrict__ yh, __half* __restrict__ yl)
{
    const int idx = blockIdx.x * 256 + threadIdx.x;
    const int d = idx & (DIN - 1), l = idx >> 11;
    float acc = cb[d];
#pragma unroll
    for (int k = 0; k < KCONV; k++) {
        const int ls = l - (KCONV - 1) + k;
        if (ls >= 0) acc = fmaf(w[d * KCONV + k], xr[(size_t)ls * (2 * DIN) + d], acc);
    }
    const float u = swishf(acc);
    xi[idx] = u;
    { __half h, lo; split2h(u, h, lo); xih[idx] = h; xil[idx] = lo; }
    const float rv = xr[(size_t)l * (2 * DIN) + DIN + d];
    const float yy = u * Dp[d] * swishf(rv);
    { __half h, lo; split2h(yy, h, lo); yh[idx] = h; yl[idx] = lo; }
}

// ---------------------------------------------------------------------------
// Selective scan, dead-zone aware (R3/R6-validated -40 cutoff logic).
// ---------------------------------------------------------------------------
__global__ void scan_kernel(const float* __restrict__ delta, const float* __restrict__ xi,
                            const float* __restrict__ xdbl, const float* __restrict__ Dp,
                            const float* __restrict__ xr, const float* __restrict__ A_log,
                            __half* __restrict__ yh, __half* __restrict__ yl)
{
    const int dn = blockIdx.x * 256 + threadIdx.x;
    const int d = dn >> 4, n = dn & 15;
    const float a = -expf(A_log[dn]);

    int l0 = 0;
    float S0 = 0.f;
    {
        float S = 0.f;        // S[L-1]
        int l = Lq - 1;
        while (true) {
            if (S <= -40.f) { l0 = l + 1; break; }
            if (l == 0)      { l0 = 0; S0 = S; break; }
            S0 = S;
            S += delta[(size_t)l * DIN + d] * a;
            --l;
        }
    }
    const int wl0 = __reduce_min_sync(0xffffffffu, l0);
    const float Dd = Dp[d];
    const bool w0 = (n == 0);

    float Scur = S0, num = 0.f;
    for (int l = wl0; l < Lq; ++l) {
        const float dv = delta[(size_t)l * DIN + d];
        const float uv = xi[(size_t)l * DIN + d];
        float part = 0.f;
        if (l >= l0) {
            if (l > l0) Scur -= dv * a;
            if (Scur > -40.f) {
                const float E = expf(Scur);
                num = fmaf(dv * uv * xdbl[(size_t)l * XDBLW + DTRANK + n], E, num);
                part = (num / (E + 1e-12f)) * xdbl[(size_t)l * XDBLW + DTRANK + Nst + n];
            }
        }
        part += __shfl_xor_sync(0xffffffffu, part, 8);
        part += __shfl_xor_sync(0xffffffffu, part, 4);
        part += __shfl_xor_sync(0xffffffffu, part, 2);
        part += __shfl_xor_sync(0xffffffffu, part, 1);
        if (w0) {
            const float rv = xr[(size_t)l * (2 * DIN) + DIN + d];
            const float yy = fmaf(uv, Dd, part) * swishf(rv);
            __half h, lo; split2h(yy, h, lo);
            yh[(size_t)l * DIN + d] = h;
            yl[(size_t)l * DIN + d] = lo;
        }
    }
}

// ---------------------------------------------------------------------------
// Launch
// ---------------------------------------------------------------------------
extern "C" void kernel_launch(void* const* d_in, const int* in_sizes, int n_in,
                              void* d_out, int out_size)
{
    const float* x      = (const float*)d_in[0];
    const float* W_in   = (const float*)d_in[1];
    const float* conv_w = (const float*)d_in[2];
    const float* conv_b = (const float*)d_in[3];
    const float* W_x    = (const float*)d_in[4];
    const float* W_dt   = (const float*)d_in[5];
    const float* b_dt   = (const float*)d_in[6];
    const float* A_log  = (const float*)d_in[7];
    const float* Dp     = (const float*)d_in[8];
    const float* W_out  = (const float*)d_in[9];
    const float* b_out  = (const float*)d_in[10];
    float* out = (float*)d_out;

    float *xr, *xi, *xdbl, *xdbl_part, *delta;
    cudaGetSymbolAddress((void**)&xr, g_xr);
    cudaGetSymbolAddress((void**)&xi, g_xi);
    cudaGetSymbolAddress((void**)&xdbl, g_xdbl);
    cudaGetSymbolAddress((void**)&xdbl_part, g_xdbl_part);
    cudaGetSymbolAddress((void**)&delta, g_delta);

    __half *xhi, *xlo, *WinT, *xih, *xil, *WxT;
    __half *dRh, *dRl, *WdtT, *yh, *yl, *WoutT;
    cudaGetSymbolAddress((void**)&xhi, g_xhi);   cudaGetSymbolAddress((void**)&xlo, g_xlo);
    cudaGetSymbolAddress((void**)&WinT, g_WinT);
    cudaGetSymbolAddress((void**)&xih, g_xihi);  cudaGetSymbolAddress((void**)&xil, g_xilo);
    cudaGetSymbolAddress((void**)&WxT, g_WxT);
    cudaGetSymbolAddress((void**)&dRh, g_dRhi);  cudaGetSymbolAddress((void**)&dRl, g_dRlo);
    cudaGetSymbolAddress((void**)&WdtT, g_WdtT);
    cudaGetSymbolAddress((void**)&yh, g_yhi);    cudaGetSymbolAddress((void**)&yl, g_ylo);
    cudaGetSymbolAddress((void**)&WoutT, g_WoutT);

    cudaFuncSetAttribute(gemm_mma<128, 0>, cudaFuncAttributeMaxDynamicSharedMemorySize, GEMM_SMEM);
    cudaFuncSetAttribute(gemm_mma<96, 0>,  cudaFuncAttributeMaxDynamicSharedMemorySize, GEMM_SMEM);
    cudaFuncSetAttribute(gemm_mma<128, 1>, cudaFuncAttributeMaxDynamicSharedMemorySize, GEMM_SMEM);
    cudaFuncSetAttribute(gemm_mma<128, 2>, cudaFuncAttributeMaxDynamicSharedMemorySize, GEMM_SMEM);

    // Weight transposes (B operands, [N, K] K-contig, single fp16)
    transpose_h_kernel<<<dim3((2 * DIN) / 32, DMODEL / 32), dim3(32, 8)>>>(W_in, WinT, DMODEL, 2 * DIN);
    transpose_h_kernel<<<dim3(XDBLW / 32, DIN / 32), dim3(32, 8)>>>(W_x, WxT, DIN, XDBLW);
    transpose_h_kernel<<<dim3(DIN / 32, DTRANK / 32), dim3(32, 8)>>>(W_dt, WdtT, DTRANK, DIN);
    transpose_h_kernel<<<dim3(DMODEL / 32, DIN / 32), dim3(32, 8)>>>(W_out, WoutT, DIN, DMODEL);
    // A operand split for GEMM1
    convert_split_kernel<<<(Lq * DMODEL) / 256, 256>>>(x, xhi, xlo, Lq * DMODEL);

    // 1) x_and_res = x @ W_in      (2048 x 4096, K=1024)
    gemm_mma<128, 0><<<dim3((2 * DIN) / 128, Lq / 128, 1), 256, GEMM_SMEM>>>(
        xhi, xlo, WinT, nullptr, xr, DMODEL, DMODEL, DMODEL, 2 * DIN, 0);

    // 2) conv + swish -> xi (fp32 + pair) and base y = u*D*swish(res)
    conv_kernel<<<(Lq * DIN) / 256, 256>>>(xr, conv_w, conv_b, Dp, xi, xih, xil, yh, yl);

    // 3) x_dbl = xi @ W_x          (2048 x 96, K=2048) split-K x8 + reduce
    gemm_mma<96, 0><<<dim3(1, Lq / 128, 8), 256, GEMM_SMEM>>>(
        xih, xil, WxT, nullptr, xdbl_part, DIN / 8, DIN, DIN, XDBLW,
        (size_t)Lq * XDBLW);
    reduce_xdbl_kernel<<<(Lq * XDBLW + 255) / 256, 256>>>(xdbl_part, xdbl);
    convert_dr_kernel<<<(Lq * DTRANK) / 256, 256>>>(xdbl, dRh, dRl);

    // 4) delta = softplus(delta_r @ W_dt + b_dt)   (2048 x 2048, K=64)
    gemm_mma<128, 2><<<dim3(DIN / 128, Lq / 128, 1), 256, GEMM_SMEM>>>(
        dRh, dRl, WdtT, b_dt, delta, DTRANK, DTRANK, DTRANK, DIN, 0);

    // 5) selective scan (active-tail only), overwrites y pair in the tail
    scan_kernel<<<(DIN * Nst) / 256, 256>>>(delta, xi, xdbl, Dp, xr, A_log, yh, yl);

    // 6) out = y @ W_out + b_out   (2048 x 1024, K=2048)
    gemm_mma<128, 1><<<dim3(DMODEL / 128, Lq / 128, 1), 256, GEMM_SMEM>>>(
        yh, yl, WoutT, b_out, out, DIN, DIN, DIN, DMODEL, 0);

    (void)in_sizes; (void)n_in; (void)out_size;
}

// round 11
// speedup vs baseline: 7.6800x; 1.0550x over previous
#include <cuda_runtime.h>
#include <cuda_bf16.h>
#include <cuda_fp16.h>
#include <cstdint>

#define Lq      2048
#define DMODEL  1024
#define DIN     2048
#define Nst     16
#define DTRANK  64
#define KCONV   4
#define XDBLW   (DTRANK + 2*Nst)   // 96

// ---------------------------------------------------------------------------
// Device scratch (allocation-free rule: __device__ globals)
// ---------------------------------------------------------------------------
__device__ float g_xr[(size_t)Lq * 2 * DIN];          // x @ W_in  (xi_pre | res)
__device__ float g_xi[(size_t)Lq * DIN];              // conv+swish output (u)
__device__ float g_xdbl[(size_t)Lq * XDBLW];          // [delta_r | B | C]
__device__ float g_xdbl_part[8 * (size_t)Lq * XDBLW]; // split-K partials
__device__ float g_delta[(size_t)Lq * DIN];           // softplus output

// A operands: exact fp16 hi/lo pairs. B operands (weights): single fp16.
__device__ __half g_xhi[(size_t)Lq * DMODEL],  g_xlo[(size_t)Lq * DMODEL];
__device__ __half g_WinT[(size_t)2*DIN * DMODEL];
__device__ __half g_xihi[(size_t)Lq * DIN], g_xilo[(size_t)Lq * DIN];
__device__ __half g_WxT[(size_t)XDBLW * DIN];
__device__ __half g_dRhi[(size_t)Lq * DTRANK], g_dRlo[(size_t)Lq * DTRANK];
__device__ __half g_WdtT[(size_t)DIN * DTRANK];
__device__ __half g_yhi[(size_t)Lq * DIN], g_ylo[(size_t)Lq * DIN];
__device__ __half g_WoutT[(size_t)DMODEL * DIN];

// ---------------------------------------------------------------------------
// Helpers
// ---------------------------------------------------------------------------
__device__ __forceinline__ float softplusf(float x) {
    return fmaxf(x, 0.f) + log1pf(expf(-fabsf(x)));
}
__device__ __forceinline__ float swishf(float x) { return x / (1.f + expf(-x)); }

__device__ __forceinline__ void split2h(float v, __half& h, __half& l) {
    h = __float2half(v);
    l = __float2half(v - __half2float(h));
}

__device__ __forceinline__ uint32_t smem_u32(const void* p) {
    uint32_t a;
    asm("{ .reg .u64 t; cvta.to.shared.u64 t, %1; cvt.u32.u64 %0, t; }" : "=r"(a) : "l"(p));
    return a;
}

// m16n8k16 row.col fp16 -> f32 accumulate (sm_80+, plain sm_103 OK)
__device__ __forceinline__ void mma16816h(float acc[4], const uint32_t a[4], const uint32_t b[2]) {
    asm volatile(
        "mma.sync.aligned.m16n8k16.row.col.f32.f16.f16.f32 "
        "{%0,%1,%2,%3}, {%4,%5,%6,%7}, {%8,%9}, {%0,%1,%2,%3};"
        : "+f"(acc[0]), "+f"(acc[1]), "+f"(acc[2]), "+f"(acc[3])
        : "r"(a[0]), "r"(a[1]), "r"(a[2]), "r"(a[3]), "r"(b[0]), "r"(b[1]));
}

__device__ __forceinline__ void ldsm_x4(uint32_t r[4], uint32_t addr) {
    asm volatile("ldmatrix.sync.aligned.m8n8.x4.shared.b16 {%0,%1,%2,%3}, [%4];"
                 : "=r"(r[0]), "=r"(r[1]), "=r"(r[2]), "=r"(r[3]) : "r"(addr));
}

#define CP_ASYNC16(dst_u32, src_ptr) \
    asm volatile("cp.async.cg.shared.global [%0], [%1], 16;" :: "r"(dst_u32), "l"(src_ptr))
#define CP_COMMIT() asm volatile("cp.async.commit_group;" ::: "memory")

// ---------------------------------------------------------------------------
// HMMA 2-pass GEMM (A fp16-pair exact, B fp16 single): C[M x N] = A * B^T
//   A: [M, lda] fp16 hi/lo (K-contig), B: [N, ldb] fp16 (K-contig)
//   CTA tile 128 x NT (128 or 96), BK = 32, 3-stage cp.async pipeline,
//   ldmatrix fragment loads. 256 threads = 8 warps (4m x 2n).
//   blockIdx.z = split-K slice: k offset z*K, C += z*czs.
//   MODE: 0 plain, 1 +bias[col], 2 softplus(v + bias[col])
// ---------------------------------------------------------------------------
#define SKp 40                          // padded smem K-stride (conflict-free)
#define MAT_BYTES (128 * SKp * 2)       // 10240 per matrix per stage
#define STAGE_BYTES (3 * MAT_BYTES)     // Ah | Al | Bh
#define GEMM_SMEM (3 * STAGE_BYTES)     // 92160

template <int NT, int MODE>
__global__ __launch_bounds__(256) void gemm_mma(
    const __half* __restrict__ Ahi, const __half* __restrict__ Alo,
    const __half* __restrict__ Bh16,
    const float* __restrict__ bias, float* __restrict__ C,
    int K, int lda, int ldb, int ldc, size_t czs)
{
    constexpr int WN = NT / 2;     // warp n-extent (64 or 48)
    constexpr int NF = WN / 8;     // n-frags per warp (8 or 6)

    extern __shared__ char dsm[];
    const uint32_t sbase = smem_u32(dsm);

    const int tid = threadIdx.x, lane = tid & 31, wid = tid >> 5;
    const int wm = wid & 3, wn = wid >> 2;
    const int g = lane >> 2, tg = lane & 3;
    const int rowBlock = blockIdx.y * 128;
    const int colBlock = blockIdx.x * NT;
    const int kbase = blockIdx.z * K;
    float* Cb = C + (size_t)blockIdx.z * czs;

    const int ldRow0 = tid >> 2, ldSeg = (tid & 3) * 8;   // cp.async coords
    const int lt = lane >> 3, lr = lane & 7;              // ldmatrix coords

    float acc[2][NF][4];
#pragma unroll
    for (int i = 0; i < 2; ++i)
#pragma unroll
        for (int j = 0; j < NF; ++j)
#pragma unroll
            for (int q = 0; q < 4; ++q) acc[i][j][q] = 0.f;

    const int nchunks = K >> 5;

    auto load_chunk = [&](int c) {
        const int k0 = kbase + (c << 5);
        const uint32_t st = sbase + (uint32_t)(c % 3) * STAGE_BYTES;
#pragma unroll
        for (int it = 0; it < 2; ++it) {
            const int row = ldRow0 + it * 64;
            const uint32_t so = (uint32_t)(row * SKp + ldSeg) * 2;
            const size_t ga = (size_t)(rowBlock + row) * lda + k0 + ldSeg;
            CP_ASYNC16(st + so,             Ahi + ga);
            CP_ASYNC16(st + MAT_BYTES + so, Alo + ga);
            if (row < NT) {
                const size_t gb = (size_t)(colBlock + row) * ldb + k0 + ldSeg;
                CP_ASYNC16(st + 2 * MAT_BYTES + so, Bh16 + gb);
            }
        }
        CP_COMMIT();
    };

    load_chunk(0);
    if (nchunks > 1) load_chunk(1);

    for (int c = 0; c < nchunks; ++c) {
        if (c + 2 < nchunks) load_chunk(c + 2);
        const int rem = nchunks - c;
        if (rem > 2)       asm volatile("cp.async.wait_group 2;" ::: "memory");
        else if (rem == 2) asm volatile("cp.async.wait_group 1;" ::: "memory");
        else               asm volatile("cp.async.wait_group 0;" ::: "memory");
        __syncthreads();

        const uint32_t st = sbase + (uint32_t)(c % 3) * STAGE_BYTES;
        const uint32_t sAh = st, sAl = st + MAT_BYTES, sBh = st + 2 * MAT_BYTES;

#pragma unroll
        for (int ks = 0; ks < 2; ++ks) {
            const int kk0 = ks * 16;
            uint32_t ah[2][4], al[2][4];
#pragma unroll
            for (int i = 0; i < 2; ++i) {
                const int ar = wm * 32 + i * 16 + (lt & 1) * 8 + lr;
                const int ac = kk0 + (lt >> 1) * 8;
                const uint32_t off = (uint32_t)(ar * SKp + ac) * 2;
                ldsm_x4(ah[i], sAh + off);
                ldsm_x4(al[i], sAl + off);
            }
            uint32_t bh[NF][2];
#pragma unroll
            for (int j = 0; j < NF; j += 2) {
                const int br = wn * WN + (j + (lt >> 1)) * 8 + lr;
                const int bc = kk0 + (lt & 1) * 8;
                const uint32_t off = (uint32_t)(br * SKp + bc) * 2;
                uint32_t t0[4];
                ldsm_x4(t0, sBh + off);
                bh[j][0] = t0[0]; bh[j][1] = t0[1];
                bh[j + 1][0] = t0[2]; bh[j + 1][1] = t0[3];
            }
#pragma unroll
            for (int i = 0; i < 2; ++i)
#pragma unroll
                for (int j = 0; j < NF; ++j) {
                    mma16816h(acc[i][j], ah[i], bh[j]);
                    mma16816h(acc[i][j], al[i], bh[j]);
                }
        }
        __syncthreads();
    }

    // Epilogue: fragment layout -> global (float2 per 8-col segment pair)
#pragma unroll
    for (int i = 0; i < 2; ++i) {
#pragma unroll
        for (int j = 0; j < NF; ++j) {
            const int r0 = rowBlock + wm * 32 + i * 16 + g;
            const int c0 = colBlock + wn * WN + j * 8 + 2 * tg;
            float v0 = acc[i][j][0], v1 = acc[i][j][1];
            float v2 = acc[i][j][2], v3 = acc[i][j][3];
            if (MODE == 1) {
                const float b0 = bias[c0], b1 = bias[c0 + 1];
                v0 += b0; v1 += b1; v2 += b0; v3 += b1;
            }
            if (MODE == 2) {
                const float b0 = bias[c0], b1 = bias[c0 + 1];
                v0 = softplusf(v0 + b0); v1 = softplusf(v1 + b1);
                v2 = softplusf(v2 + b0); v3 = softplusf(v3 + b1);
            }
            *(float2*)&Cb[(size_t)(r0    ) * ldc + c0] = make_float2(v0, v1);
            *(float2*)&Cb[(size_t)(r0 + 8) * ldc + c0] = make_float2(v2, v3);
        }
    }
}

// ---------------------------------------------------------------------------
// Fused preprocessing: all 4 weight transposes (fp32 [K,N] -> fp16 [N,K])
// plus the x hi/lo split, in ONE launch. Block-range dispatch.
// ---------------------------------------------------------------------------
#define NB_WIN  4096
#define NB_WX   192
#define NB_WDT  128
#define NB_WOUT 2048
#define NB_XSPL 1024
#define NB_TOTAL (NB_WIN + NB_WX + NB_WDT + NB_WOUT + NB_XSPL)

__device__ __forceinline__ void transpose_tile(
    const float* __restrict__ W, __half* __restrict__ Th,
    int K, int N, int kt, int nt, float (*t)[33], int tx, int ty)
{
    const int n0 = nt * 32, k0 = kt * 32;
#pragma unroll
    for (int j = 0; j < 32; j += 8)
        t[ty + j][tx] = W[(size_t)(k0 + ty + j) * N + n0 + tx];
    __syncthreads();
#pragma unroll
    for (int j = 0; j < 32; j += 8)
        Th[(size_t)(n0 + ty + j) * K + k0 + tx] = __float2half(t[tx][ty + j]);
}

__global__ __launch_bounds__(256) void prep_kernel(
    const float* __restrict__ W_in, const float* __restrict__ W_x,
    const float* __restrict__ W_dt, const float* __restrict__ W_out,
    const float* __restrict__ x,
    __half* __restrict__ WinT, __half* __restrict__ WxT,
    __half* __restrict__ WdtT, __half* __restrict__ WoutT,
    __half* __restrict__ xhi, __half* __restrict__ xlo)
{
    __shared__ float t[32][33];
    const int b = blockIdx.x;
    const int tx = threadIdx.x & 31, ty = threadIdx.x >> 5;   // 32 x 8

    if (b < NB_WIN) {
        // W_in: N-tiles = 4096/32 = 128
        transpose_tile(W_in, WinT, DMODEL, 2 * DIN, b / 128, b % 128, t, tx, ty);
    } else if (b < NB_WIN + NB_WX) {
        const int r = b - NB_WIN;          // N-tiles = 96/32 = 3
        transpose_tile(W_x, WxT, DIN, XDBLW, r / 3, r % 3, t, tx, ty);
    } else if (b < NB_WIN + NB_WX + NB_WDT) {
        const int r = b - NB_WIN - NB_WX;  // N-tiles = 2048/32 = 64
        transpose_tile(W_dt, WdtT, DTRANK, DIN, r / 64, r % 64, t, tx, ty);
    } else if (b < NB_WIN + NB_WX + NB_WDT + NB_WOUT) {
        const int r = b - NB_WIN - NB_WX - NB_WDT;  // N-tiles = 1024/32 = 32
        transpose_tile(W_out, WoutT, DIN, DMODEL, r / 32, r % 32, t, tx, ty);
    } else {
        const int r = b - (NB_WIN + NB_WX + NB_WDT + NB_WOUT);
        const int base = r * 2048 + threadIdx.x;
#pragma unroll
        for (int j = 0; j < 8; ++j) {
            const int i = base + j * 256;
            __half h, l; split2h(x[i], h, l);
            xhi[i] = h; xlo[i] = l;
        }
    }
}

// ---------------------------------------------------------------------------
// Split-K reduce for x_dbl (fixed order -> deterministic) + fused dR hi/lo
// ---------------------------------------------------------------------------
__global__ void reduce_xdbl_kernel(const float* __restrict__ part, float* __restrict__ out,
                                   __half* __restrict__ Rh, __half* __restrict__ Rl)
{
    const int i = blockIdx.x * blockDim.x + threadIdx.x;
    if (i >= Lq * XDBLW) return;
    float s = 0.f;
#pragma unroll
    for (int k = 0; k < 8; k++) s += part[(size_t)k * Lq * XDBLW + i];
    out[i] = s;
    const int c = i % XDBLW;
    if (c < DTRANK) {
        const int l = i / XDBLW;
        __half h, lo; split2h(s, h, lo);
        Rh[l * DTRANK + c] = h; Rl[l * DTRANK + c] = lo;
    }
}

// ---------------------------------------------------------------------------
// Depthwise causal conv1d + swish; emits xi fp32 + fp16 pair and base
// y = u*D*swish(res) as fp16 pair
// ---------------------------------------------------------------------------
__global__ void conv_kernel(const float* __restrict__ xr, const float* __restrict__ w,
                            const float* __restrict__ cb, const float* __restrict__ Dp,
                            float* __restrict__ xi,
                            __half* __restrict__ xih, __half* __restrict__ xil,
                            __half* __restrict__ yh, __half* __restrict__ yl)
{
    const int idx = blockIdx.x * 256 + threadIdx.x;
    const int d = idx & (DIN - 1), l = idx >> 11;
    float acc = cb[d];
#pragma unroll
    for (int k = 0; k < KCONV; k++) {
        const int ls = l - (KCONV - 1) + k;
        if (ls >= 0) acc = fmaf(w[d * KCONV + k], xr[(size_t)ls * (2 * DIN) + d], acc);
    }
    const float u = swishf(acc);
    xi[idx] = u;
    { __half h, lo; split2h(u, h, lo); xih[idx] = h; xil[idx] = lo; }
    const float rv = xr[(size_t)l * (2 * DIN) + DIN + d];
    const float yy = u * Dp[d] * swishf(rv);
    { __half h, lo; split2h(yy, h, lo); yh[idx] = h; yl[idx] = lo; }
}

// ---------------------------------------------------------------------------
// Selective scan, dead-zone aware (R3/R6-validated -40 cutoff logic).
// ---------------------------------------------------------------------------
__global__ void scan_kernel(const float* __restrict__ delta, const float* __restrict__ xi,
                            const float* __restrict__ xdbl, const float* __restrict__ Dp,
                            const float* __restrict__ xr, const float* __restrict__ A_log,
                            __half* __restrict__ yh, __half* __restrict__ yl)
{
    const int dn = blockIdx.x * 256 + threadIdx.x;
    const int d = dn >> 4, n = dn & 15;
    const float a = -expf(A_log[dn]);

    int l0 = 0;
    float S0 = 0.f;
    {
        float S = 0.f;        // S[L-1]
        int l = Lq - 1;
        while (true) {
            if (S <= -40.f) { l0 = l + 1; break; }
            if (l == 0)      { l0 = 0; S0 = S; break; }
            S0 = S;
            S += delta[(size_t)l * DIN + d] * a;
            --l;
        }
    }
    const int wl0 = __reduce_min_sync(0xffffffffu, l0);
    const float Dd = Dp[d];
    const bool w0 = (n == 0);

    float Scur = S0, num = 0.f;
    for (int l = wl0; l < Lq; ++l) {
        const float dv = delta[(size_t)l * DIN + d];
        const float uv = xi[(size_t)l * DIN + d];
        float part = 0.f;
        if (l >= l0) {
            if (l > l0) Scur -= dv * a;
            if (Scur > -40.f) {
                const float E = expf(Scur);
                num = fmaf(dv * uv * xdbl[(size_t)l * XDBLW + DTRANK + n], E, num);
                part = (num / (E + 1e-12f)) * xdbl[(size_t)l * XDBLW + DTRANK + Nst + n];
            }
        }
        part += __shfl_xor_sync(0xffffffffu, part, 8);
        part += __shfl_xor_sync(0xffffffffu, part, 4);
        part += __shfl_xor_sync(0xffffffffu, part, 2);
        part += __shfl_xor_sync(0xffffffffu, part, 1);
        if (w0) {
            const float rv = xr[(size_t)l * (2 * DIN) + DIN + d];
            const float yy = fmaf(uv, Dd, part) * swishf(rv);
            __half h, lo; split2h(yy, h, lo);
            yh[(size_t)l * DIN + d] = h;
            yl[(size_t)l * DIN + d] = lo;
        }
    }
}

// ---------------------------------------------------------------------------
// Launch
// ---------------------------------------------------------------------------
extern "C" void kernel_launch(void* const* d_in, const int* in_sizes, int n_in,
                              void* d_out, int out_size)
{
    const float* x      = (const float*)d_in[0];
    const float* W_in   = (const float*)d_in[1];
    const float* conv_w = (const float*)d_in[2];
    const float* conv_b = (const float*)d_in[3];
    const float* W_x    = (const float*)d_in[4];
    const float* W_dt   = (const float*)d_in[5];
    const float* b_dt   = (const float*)d_in[6];
    const float* A_log  = (const float*)d_in[7];
    const float* Dp     = (const float*)d_in[8];
    const float* W_out  = (const float*)d_in[9];
    const float* b_out  = (const float*)d_in[10];
    float* out = (float*)d_out;

    float *xr, *xi, *xdbl, *xdbl_part, *delta;
    cudaGetSymbolAddress((void**)&xr, g_xr);
    cudaGetSymbolAddress((void**)&xi, g_xi);
    cudaGetSymbolAddress((void**)&xdbl, g_xdbl);
    cudaGetSymbolAddress((void**)&xdbl_part, g_xdbl_part);
    cudaGetSymbolAddress((void**)&delta, g_delta);

    __half *xhi, *xlo, *WinT, *xih, *xil, *WxT;
    __half *dRh, *dRl, *WdtT, *yh, *yl, *WoutT;
    cudaGetSymbolAddress((void**)&xhi, g_xhi);   cudaGetSymbolAddress((void**)&xlo, g_xlo);
    cudaGetSymbolAddress((void**)&WinT, g_WinT);
    cudaGetSymbolAddress((void**)&xih, g_xihi);  cudaGetSymbolAddress((void**)&xil, g_xilo);
    cudaGetSymbolAddress((void**)&WxT, g_WxT);
    cudaGetSymbolAddress((void**)&dRh, g_dRhi);  cudaGetSymbolAddress((void**)&dRl, g_dRlo);
    cudaGetSymbolAddress((void**)&WdtT, g_WdtT);
    cudaGetSymbolAddress((void**)&yh, g_yhi);    cudaGetSymbolAddress((void**)&yl, g_ylo);
    cudaGetSymbolAddress((void**)&WoutT, g_WoutT);

    cudaFuncSetAttribute(gemm_mma<128, 0>, cudaFuncAttributeMaxDynamicSharedMemorySize, GEMM_SMEM);
    cudaFuncSetAttribute(gemm_mma<96, 0>,  cudaFuncAttributeMaxDynamicSharedMemorySize, GEMM_SMEM);
    cudaFuncSetAttribute(gemm_mma<128, 1>, cudaFuncAttributeMaxDynamicSharedMemorySize, GEMM_SMEM);
    cudaFuncSetAttribute(gemm_mma<128, 2>, cudaFuncAttributeMaxDynamicSharedMemorySize, GEMM_SMEM);

    // 0) All preprocessing in ONE launch (4 weight transposes + x hi/lo split)
    prep_kernel<<<NB_TOTAL, 256>>>(W_in, W_x, W_dt, W_out, x,
                                   WinT, WxT, WdtT, WoutT, xhi, xlo);

    // 1) x_and_res = x @ W_in      (2048 x 4096, K=1024)
    gemm_mma<128, 0><<<dim3((2 * DIN) / 128, Lq / 128, 1), 256, GEMM_SMEM>>>(
        xhi, xlo, WinT, nullptr, xr, DMODEL, DMODEL, DMODEL, 2 * DIN, 0);

    // 2) conv + swish -> xi (fp32 + pair) and base y = u*D*swish(res)
    conv_kernel<<<(Lq * DIN) / 256, 256>>>(xr, conv_w, conv_b, Dp, xi, xih, xil, yh, yl);

    // 3) x_dbl = xi @ W_x          (2048 x 96, K=2048) split-K x8 + fused reduce/dR
    gemm_mma<96, 0><<<dim3(1, Lq / 128, 8), 256, GEMM_SMEM>>>(
        xih, xil, WxT, nullptr, xdbl_part, DIN / 8, DIN, DIN, XDBLW,
        (size_t)Lq * XDBLW);
    reduce_xdbl_kernel<<<(Lq * XDBLW + 255) / 256, 256>>>(xdbl_part, xdbl, dRh, dRl);

    // 4) delta = softplus(delta_r @ W_dt + b_dt)   (2048 x 2048, K=64)
    gemm_mma<128, 2><<<dim3(DIN / 128, Lq / 128, 1), 256, GEMM_SMEM>>>(
        dRh, dRl, WdtT, b_dt, delta, DTRANK, DTRANK, DTRANK, DIN, 0);

    // 5) selective scan (active-tail only), overwrites y pair in the tail
    scan_kernel<<<(DIN * Nst) / 256, 256>>>(delta, xi, xdbl, Dp, xr, A_log, yh, yl);

    // 6) out = y @ W_out + b_out   (2048 x 1024, K=2048)
    gemm_mma<128, 1><<<dim3(DMODEL / 128, Lq / 128, 1), 256, GEMM_SMEM>>>(
        yh, yl, WoutT, b_out, out, DIN, DIN, DIN, DMODEL, 0);

    (void)in_sizes; (void)n_in; (void)out_size;
}